// round 3
// baseline (speedup 1.0000x reference)
#include <cuda_runtime.h>
#include <cstdint>

// Problem constants
#define B_SZ   8
#define T_SZ   4096
#define D_SZ   768
#define NH     12
#define HD     64
#define NS     64
#define ALPHAF 0.1f
#define BT     (B_SZ * T_SZ)   // 32768
#define HM     (NH * NS)       // 768 (= D_SZ, coincidence of shapes)

// Scratch (static device globals: allocation APIs are forbidden)
__device__ float g_C[HM * D_SZ];                 // fused (W_tok, prototypes) matrix, 2.4 MB
__device__ float g_w[(size_t)BT * HM];           // scores -> w -> w_eff (in place), 96 MB
__device__ float g_res[B_SZ * NH * NS];          // total suffix product per (b,h,m)

// ---------------------------------------------------------------------------
// K0: C[h*64+m, d] = (1/8) * sum_j W_tok[h*64+j, d] * proto[m*768 + h*64 + j]
// ---------------------------------------------------------------------------
__global__ void k_build_C(const float* __restrict__ W, const float* __restrict__ proto) {
    int idx = blockIdx.x * blockDim.x + threadIdx.x;
    if (idx >= HM * D_SZ) return;
    int d  = idx % D_SZ;
    int hm = idx / D_SZ;
    int h = hm / NS, m = hm % NS;
    const float* wcol = W + (size_t)(h * HD) * D_SZ + d;   // stride D_SZ over j
    const float* prow = proto + (size_t)m * D_SZ + h * HD; // contiguous over j
    float acc = 0.f;
#pragma unroll 8
    for (int j = 0; j < HD; j++) acc += wcol[(size_t)j * D_SZ] * prow[j];
    g_C[idx] = acc * 0.125f;  // 1/sqrt(64)
}

// ---------------------------------------------------------------------------
// K1: scores[bt, hm] = sum_k H[bt, k] * C[hm, k]
//     128x128 tile, BK=16, 256 threads, 8x8 microtile, register prefetch.
// ---------------------------------------------------------------------------
__global__ void __launch_bounds__(256) k_gemm(const float* __restrict__ A) {
    __shared__ float As[16][128];
    __shared__ float Bs[16][128];

    const int tid = threadIdx.x;
    const int m0 = blockIdx.y * 128;
    const int n0 = blockIdx.x * 128;
    const int ty = tid >> 4;   // 0..15 (M direction)
    const int tx = tid & 15;   // 0..15 (N direction)

    const int rl = tid >> 2;   // 0..63 : tile row for loads
    const int kg = tid & 3;    // 0..3  : which float4 along K

    const float* Abase = A   + (size_t)(m0 + rl) * D_SZ + kg * 4;
    const float* Bbase = g_C + (size_t)(n0 + rl) * D_SZ + kg * 4;
    const size_t rowoff = (size_t)64 * D_SZ;

    float4 ra0 = *(const float4*)(Abase);
    float4 ra1 = *(const float4*)(Abase + rowoff);
    float4 rb0 = *(const float4*)(Bbase);
    float4 rb1 = *(const float4*)(Bbase + rowoff);

    float acc[8][8];
#pragma unroll
    for (int i = 0; i < 8; i++)
#pragma unroll
        for (int j = 0; j < 8; j++) acc[i][j] = 0.f;

    const int KT = D_SZ / 16;  // 48
    for (int kt = 0; kt < KT; kt++) {
        const int kb = kg * 4;
        As[kb + 0][rl]      = ra0.x; As[kb + 1][rl]      = ra0.y;
        As[kb + 2][rl]      = ra0.z; As[kb + 3][rl]      = ra0.w;
        As[kb + 0][rl + 64] = ra1.x; As[kb + 1][rl + 64] = ra1.y;
        As[kb + 2][rl + 64] = ra1.z; As[kb + 3][rl + 64] = ra1.w;
        Bs[kb + 0][rl]      = rb0.x; Bs[kb + 1][rl]      = rb0.y;
        Bs[kb + 2][rl]      = rb0.z; Bs[kb + 3][rl]      = rb0.w;
        Bs[kb + 0][rl + 64] = rb1.x; Bs[kb + 1][rl + 64] = rb1.y;
        Bs[kb + 2][rl + 64] = rb1.z; Bs[kb + 3][rl + 64] = rb1.w;
        __syncthreads();

        if (kt + 1 < KT) {
            const float* An = Abase + (size_t)(kt + 1) * 16;
            const float* Bn = Bbase + (size_t)(kt + 1) * 16;
            ra0 = *(const float4*)(An);
            ra1 = *(const float4*)(An + rowoff);
            rb0 = *(const float4*)(Bn);
            rb1 = *(const float4*)(Bn + rowoff);
        }

#pragma unroll
        for (int kk = 0; kk < 16; kk++) {
            float4 a0 = *(const float4*)&As[kk][ty * 8];
            float4 a1 = *(const float4*)&As[kk][ty * 8 + 4];
            float4 b0 = *(const float4*)&Bs[kk][tx * 8];
            float4 b1 = *(const float4*)&Bs[kk][tx * 8 + 4];
            float av[8] = {a0.x, a0.y, a0.z, a0.w, a1.x, a1.y, a1.z, a1.w};
            float bv[8] = {b0.x, b0.y, b0.z, b0.w, b1.x, b1.y, b1.z, b1.w};
#pragma unroll
            for (int i = 0; i < 8; i++)
#pragma unroll
                for (int j = 0; j < 8; j++) acc[i][j] = fmaf(av[i], bv[j], acc[i][j]);
        }
        __syncthreads();
    }

#pragma unroll
    for (int i = 0; i < 8; i++) {
        float* dst = g_w + (size_t)(m0 + ty * 8 + i) * HM + n0 + tx * 8;
        float4 o0 = {acc[i][0], acc[i][1], acc[i][2], acc[i][3]};
        float4 o1 = {acc[i][4], acc[i][5], acc[i][6], acc[i][7]};
        *(float4*)dst       = o0;
        *(float4*)(dst + 4) = o1;
    }
}

// ---------------------------------------------------------------------------
// K2: softmax over m (64 values) per row r = bt*12 + h; base offset = r*64.
// One warp per row, 8 rows per 256-thread block.
// ---------------------------------------------------------------------------
__global__ void __launch_bounds__(256) k_softmax() {
    int r = blockIdx.x * 8 + (threadIdx.x >> 5);
    int lane = threadIdx.x & 31;
    float* p = g_w + (size_t)r * 64;
    float v0 = p[lane], v1 = p[lane + 32];
    float mx = fmaxf(v0, v1);
#pragma unroll
    for (int off = 16; off >= 1; off >>= 1)
        mx = fmaxf(mx, __shfl_xor_sync(0xFFFFFFFFu, mx, off));
    float e0 = __expf(v0 - mx), e1 = __expf(v1 - mx);
    float s = e0 + e1;
#pragma unroll
    for (int off = 16; off >= 1; off >>= 1)
        s += __shfl_xor_sync(0xFFFFFFFFu, s, off);
    float inv = 1.0f / s;
    p[lane]      = e0 * inv;
    p[lane + 32] = e1 * inv;
}

// ---------------------------------------------------------------------------
// K3: suffix-product scan over T per (b,h,m); writes w_eff in place + residual.
// One 1024-thread block per (b,h): thread = (chunk c in 0..15, state m in 0..63).
// ---------------------------------------------------------------------------
__global__ void __launch_bounds__(1024) k_scan() {
    const int bh = blockIdx.x;             // b*12 + h
    const int b = bh / NH, h = bh % NH;
    const int c = threadIdx.x >> 6;        // 0..15
    const int m = threadIdx.x & 63;
    const int CH = T_SZ / 16;              // 256
    const size_t base = (size_t)b * T_SZ * HM + h * NS + m;  // + t*HM

    const int t0 = c * CH;
    float prod = 1.f;
    for (int t = t0 + CH - 1; t >= t0; t--) {
        float w = g_w[base + (size_t)t * HM];
        prod *= (1.f - ALPHAF * w);
    }

    __shared__ float cp[16][64];
    cp[c][m] = prod;
    __syncthreads();

    float off = 1.f;
    for (int cc = c + 1; cc < 16; cc++) off *= cp[cc][m];

    if (c == 0) g_res[bh * NS + m] = off * prod;  // product over all t

    float run = off;  // product of g over t' >= t0+CH
    for (int t = t0 + CH - 1; t >= t0; t--) {
        size_t idx = base + (size_t)t * HM;
        float w = g_w[idx];
        g_w[idx] = ALPHAF * w * run;   // w_eff = a*w*suffix_exc
        run *= (1.f - ALPHAF * w);
    }
}

// ---------------------------------------------------------------------------
// K4a: out[b, m, h*64+j] = s0[m, h*64+j] * residual[b,h,m]   (also zero-inits)
// ---------------------------------------------------------------------------
__global__ void k_init_out(const float* __restrict__ s0, float* __restrict__ out) {
    int idx = blockIdx.x * blockDim.x + threadIdx.x;
    if (idx >= B_SZ * NS * D_SZ) return;
    int dj = idx % D_SZ;
    int m  = (idx / D_SZ) % NS;
    int b  = idx / (D_SZ * NS);
    int h  = dj / HD;
    out[idx] = s0[(size_t)m * D_SZ + dj] * g_res[(b * NH + h) * NS + m];
}

// ---------------------------------------------------------------------------
// K4b: out[b, m, h*64+j] += sum_t w_eff[b,h,t,m] * H[b,t,h*64+j]
// grid = (96 bh, 8 t-splits); 256 threads; 4x4 register tile; fp32 atomics.
// ---------------------------------------------------------------------------
__global__ void __launch_bounds__(256) k_accum(const float* __restrict__ H,
                                               float* __restrict__ out) {
    const int bh = blockIdx.x;
    const int b = bh / NH, h = bh % NH;
    const int tstart = blockIdx.y * (T_SZ / 8);  // 512 t's per block

    __shared__ float sw[8][64];
    __shared__ float sh[8][64];

    const int tid = threadIdx.x;
    const int tm = tid >> 4;   // 0..15 -> m tile
    const int tj = tid & 15;   // 0..15 -> j tile

    float acc[4][4];
#pragma unroll
    for (int i = 0; i < 4; i++)
#pragma unroll
        for (int j = 0; j < 4; j++) acc[i][j] = 0.f;

    for (int tt = 0; tt < T_SZ / 8; tt += 8) {
        __syncthreads();
#pragma unroll
        for (int l = tid; l < 512; l += 256) {
            int lt = l >> 6, lm = l & 63;
            int t = tstart + tt + lt;
            size_t bt = (size_t)b * T_SZ + t;
            sw[lt][lm] = g_w[bt * HM + h * NS + lm];
            sh[lt][lm] = H[bt * D_SZ + h * HD + lm];
        }
        __syncthreads();
#pragma unroll
        for (int lt = 0; lt < 8; lt++) {
            float4 a4 = *(const float4*)&sw[lt][tm * 4];
            float4 b4 = *(const float4*)&sh[lt][tj * 4];
            float av[4] = {a4.x, a4.y, a4.z, a4.w};
            float bv[4] = {b4.x, b4.y, b4.z, b4.w};
#pragma unroll
            for (int i = 0; i < 4; i++)
#pragma unroll
                for (int j = 0; j < 4; j++) acc[i][j] = fmaf(av[i], bv[j], acc[i][j]);
        }
    }

#pragma unroll
    for (int i = 0; i < 4; i++) {
        int m = tm * 4 + i;
        float* dst = out + ((size_t)b * NS + m) * D_SZ + h * HD + tj * 4;
#pragma unroll
        for (int j = 0; j < 4; j++) atomicAdd(dst + j, acc[i][j]);
    }
}

// ---------------------------------------------------------------------------
extern "C" void kernel_launch(void* const* d_in, const int* in_sizes, int n_in,
                              void* d_out, int out_size) {
    const float* H     = (const float*)d_in[0];   // [8, 4096, 768]
    const float* proto = (const float*)d_in[1];   // [64, 768]
    const float* W     = (const float*)d_in[2];   // [768, 768]
    const float* s0    = (const float*)d_in[3];   // [1, 64, 768]
    float* out = (float*)d_out;                   // [8, 64, 768]
    (void)in_sizes; (void)n_in; (void)out_size;

    k_build_C<<<(HM * D_SZ + 255) / 256, 256>>>(W, proto);

    dim3 g1(HM / 128, BT / 128);   // (6, 256)
    k_gemm<<<g1, 256>>>(H);

    k_softmax<<<(BT * NH) / 8, 256>>>();

    k_scan<<<B_SZ * NH, 1024>>>();

    k_init_out<<<(B_SZ * NS * D_SZ + 255) / 256, 256>>>(s0, out);

    dim3 g4(B_SZ * NH, 8);
    k_accum<<<g4, 256>>>(H, out);
}

// round 6
// speedup vs baseline: 2.4042x; 2.4042x over previous
#include <cuda_runtime.h>
#include <cuda_bf16.h>
#include <cstdint>

// Problem constants
#define B_SZ   8
#define T_SZ   4096
#define D_SZ   768
#define NH     12
#define HD     64
#define NS     64
#define ALPHAF 0.1f
#define BT     (B_SZ * T_SZ)   // 32768
#define HM     (NH * NS)       // 768

// Scratch (static device globals: allocation APIs are forbidden)
__device__ float g_C[HM * D_SZ];                 // fused (W_tok, prototypes), 2.4 MB
__device__ float g_w[(size_t)BT * HM];           // w -> w_eff (in place), 96 MB
__device__ float g_res[B_SZ * NH * NS];          // total suffix product per (b,h,m)
__device__ float g_cp[B_SZ * NH * 64 * 64];      // per-chunk products / suffix offsets

// ============================ helpers ======================================
__device__ __forceinline__ uint32_t smem_u32(const void* p) {
    uint32_t a;
    asm("{ .reg .u64 t; cvta.to.shared.u64 t, %1; cvt.u32.u64 %0, t; }"
        : "=r"(a) : "l"(p));
    return a;
}
// result = {hi16 = bf16(h), lo16 = bf16(l)}
__device__ __forceinline__ uint32_t cvt_bf16x2(float h, float l) {
    uint32_t r;
    asm("cvt.rn.bf16x2.f32 %0, %1, %2;" : "=r"(r) : "f"(h), "f"(l));
    return r;
}
__device__ __forceinline__ void ldm_x4(uint32_t* r, uint32_t addr) {
    asm volatile("ldmatrix.sync.aligned.m8n8.x4.shared.b16 {%0,%1,%2,%3}, [%4];"
        : "=r"(r[0]), "=r"(r[1]), "=r"(r[2]), "=r"(r[3]) : "r"(addr));
}
__device__ __forceinline__ void mma_bf16(float* d, const uint32_t* a, const uint32_t* b) {
    asm volatile(
        "mma.sync.aligned.m16n8k16.row.col.f32.bf16.bf16.f32 "
        "{%0,%1,%2,%3}, {%4,%5,%6,%7}, {%8,%9}, {%0,%1,%2,%3};"
        : "+f"(d[0]), "+f"(d[1]), "+f"(d[2]), "+f"(d[3])
        : "r"(a[0]), "r"(a[1]), "r"(a[2]), "r"(a[3]), "r"(b[0]), "r"(b[1]));
}

// ---------------------------------------------------------------------------
// K0: C[h*64+m, d] = (1/8) * sum_j W_tok[h*64+j, d] * proto[m*768 + h*64 + j]
// ---------------------------------------------------------------------------
__global__ void k_build_C(const float* __restrict__ W, const float* __restrict__ proto) {
    int idx = blockIdx.x * blockDim.x + threadIdx.x;
    if (idx >= HM * D_SZ) return;
    int d  = idx % D_SZ;
    int hm = idx / D_SZ;
    int h = hm / NS, m = hm % NS;
    const float* wcol = W + (size_t)(h * HD) * D_SZ + d;
    const float* prow = proto + (size_t)m * D_SZ + h * HD;
    float acc = 0.f;
#pragma unroll 8
    for (int j = 0; j < HD; j++) acc += wcol[(size_t)j * D_SZ] * prow[j];
    g_C[idx] = acc * 0.125f;
}

// ---------------------------------------------------------------------------
// K1: mma.sync bf16x3 GEMM (scores) + fused per-head softmax epilogue.
// CTA tile 128(m) x 128(n=2 heads); 8 warps in 4(m) x 2(n); warp tile 32x64.
// Each warp covers one full head -> in-register softmax (shfl over quad-lanes).
// K processed in chunks of 32, double-buffered smem (Ah|Al|Bh|Bl per stage).
// Row pitch 80B => ldmatrix phase-conflict-free.
// ---------------------------------------------------------------------------
#define STG_BYTES   40960                 // 4 arrays * 128 rows * 80B
#define ARR_BYTES   10240                 // 128 * 80
#define GEMM_SMEM   (2 * STG_BYTES)       // 81920

__global__ void __launch_bounds__(256, 1) k_gemm_mma(const float* __restrict__ A) {
    extern __shared__ char smem[];
    const uint32_t sbase = smem_u32(smem);
    const int tid = threadIdx.x;
    const int wid = tid >> 5;
    const int lid = tid & 31;
    const int warpM = wid & 3;            // 0..3  (32-row band)
    const int warpN = wid >> 2;           // 0..1  (64-col head)
    const int m0 = blockIdx.y * 128;
    const int n0 = blockIdx.x * 128;

    // per-thread global staging regs (held across math for overlap)
    float4 ga[4], gb[4];
    const int grow = tid >> 3;            // 0..31 base row (x4 via +? no: j = tid+256*i)
    (void)grow;

    auto gload = [&](int kt) {
        const int k0 = kt * 32;
#pragma unroll
        for (int i = 0; i < 4; i++) {
            int j = tid + 256 * i;        // 0..1023
            int row = j >> 3, q = j & 7;
            ga[i] = *(const float4*)(A   + (size_t)(m0 + row) * D_SZ + k0 + q * 4);
            gb[i] = *(const float4*)(g_C + (size_t)(n0 + row) * D_SZ + k0 + q * 4);
        }
    };
    auto sstore = [&](int s) {
        char* sb = smem + s * STG_BYTES;
#pragma unroll
        for (int i = 0; i < 4; i++) {
            int j = tid + 256 * i;
            int row = j >> 3, q = j & 7;
            uint32_t off = (uint32_t)(row * 80 + q * 8);
            // A split
            uint32_t h01 = cvt_bf16x2(ga[i].y, ga[i].x);
            uint32_t h23 = cvt_bf16x2(ga[i].w, ga[i].z);
            float f0 = __uint_as_float(h01 << 16);
            float f1 = __uint_as_float(h01 & 0xFFFF0000u);
            float f2 = __uint_as_float(h23 << 16);
            float f3 = __uint_as_float(h23 & 0xFFFF0000u);
            *(uint2*)(sb + off) = make_uint2(h01, h23);
            *(uint2*)(sb + ARR_BYTES + off) =
                make_uint2(cvt_bf16x2(ga[i].y - f1, ga[i].x - f0),
                           cvt_bf16x2(ga[i].w - f3, ga[i].z - f2));
            // B split
            uint32_t g01 = cvt_bf16x2(gb[i].y, gb[i].x);
            uint32_t g23 = cvt_bf16x2(gb[i].w, gb[i].z);
            float e0 = __uint_as_float(g01 << 16);
            float e1 = __uint_as_float(g01 & 0xFFFF0000u);
            float e2 = __uint_as_float(g23 << 16);
            float e3 = __uint_as_float(g23 & 0xFFFF0000u);
            *(uint2*)(sb + 2 * ARR_BYTES + off) = make_uint2(g01, g23);
            *(uint2*)(sb + 3 * ARR_BYTES + off) =
                make_uint2(cvt_bf16x2(gb[i].y - e1, gb[i].x - e0),
                           cvt_bf16x2(gb[i].w - e3, gb[i].z - e2));
        }
    };

    float acc[2][8][4];
#pragma unroll
    for (int mf = 0; mf < 2; mf++)
#pragma unroll
        for (int nf = 0; nf < 8; nf++)
#pragma unroll
            for (int c = 0; c < 4; c++) acc[mf][nf][c] = 0.f;

    // ldmatrix lane-address components (constant per lane)
    const int a_row_add = (lid & 7) + ((lid >> 3) & 1) * 8;   // within 16-row frag
    const int a_k_add   = (lid >> 4) * 16;                    // byte offset (k half)
    const int b_row_add = (lid & 7) + ((lid >> 4) & 1) * 8;   // within 16 n-rows
    const int b_k_add   = ((lid >> 3) & 1) * 16;              // byte offset (k half)

    auto domath = [&](int s) {
        const uint32_t stg = sbase + s * STG_BYTES;
#pragma unroll
        for (int ks = 0; ks < 2; ks++) {
            const int kB = ks * 32;       // 16 bf16 = 32 bytes
            uint32_t aH[2][4], aL[2][4];
#pragma unroll
            for (int mf = 0; mf < 2; mf++) {
                int row = warpM * 32 + mf * 16 + a_row_add;
                uint32_t addr = stg + (uint32_t)(row * 80 + kB + a_k_add);
                ldm_x4(aH[mf], addr);
                ldm_x4(aL[mf], addr + ARR_BYTES);
            }
            uint32_t bH[4][4], bL[4][4];
#pragma unroll
            for (int nf2 = 0; nf2 < 4; nf2++) {
                int nrow = warpN * 64 + nf2 * 16 + b_row_add;
                uint32_t addr = stg + 2 * ARR_BYTES + (uint32_t)(nrow * 80 + kB + b_k_add);
                ldm_x4(bH[nf2], addr);
                ldm_x4(bL[nf2], addr + ARR_BYTES);
            }
#pragma unroll
            for (int mf = 0; mf < 2; mf++)
#pragma unroll
                for (int nf = 0; nf < 8; nf++) {
                    const uint32_t* bh = &bH[nf >> 1][(nf & 1) * 2];
                    const uint32_t* bl = &bL[nf >> 1][(nf & 1) * 2];
                    mma_bf16(acc[mf][nf], aH[mf], bh);
                    mma_bf16(acc[mf][nf], aH[mf], bl);
                    mma_bf16(acc[mf][nf], aL[mf], bh);
                }
        }
    };

    const int KT = D_SZ / 32;  // 24
    gload(0);
    sstore(0);
    __syncthreads();
    for (int kt = 0; kt < KT; kt++) {
        if (kt + 1 < KT) gload(kt + 1);
        domath(kt & 1);
        if (kt + 1 < KT) {
            sstore((kt + 1) & 1);
            __syncthreads();
        }
    }

    // Epilogue: softmax per row over this warp's 64-col head, write w.
    const int colq = (lid & 3) * 2;                   // quad-lane col offset
#pragma unroll
    for (int mf = 0; mf < 2; mf++) {
#pragma unroll
        for (int half = 0; half < 2; half++) {
            const int row = m0 + warpM * 32 + mf * 16 + (lid >> 2) + half * 8;
            // max over this lane's 16 cols
            float mx = -3.4e38f;
#pragma unroll
            for (int nf = 0; nf < 8; nf++) {
                mx = fmaxf(mx, acc[mf][nf][half * 2]);
                mx = fmaxf(mx, acc[mf][nf][half * 2 + 1]);
            }
            mx = fmaxf(mx, __shfl_xor_sync(0xFFFFFFFFu, mx, 1));
            mx = fmaxf(mx, __shfl_xor_sync(0xFFFFFFFFu, mx, 2));
            float s = 0.f;
            float ev[8][2];
#pragma unroll
            for (int nf = 0; nf < 8; nf++) {
                ev[nf][0] = __expf(acc[mf][nf][half * 2]     - mx);
                ev[nf][1] = __expf(acc[mf][nf][half * 2 + 1] - mx);
                s += ev[nf][0] + ev[nf][1];
            }
            s += __shfl_xor_sync(0xFFFFFFFFu, s, 1);
            s += __shfl_xor_sync(0xFFFFFFFFu, s, 2);
            const float inv = 1.0f / s;
            float* dst = g_w + (size_t)row * HM + n0 + warpN * 64 + colq;
#pragma unroll
            for (int nf = 0; nf < 8; nf++) {
                float2 o = {ev[nf][0] * inv, ev[nf][1] * inv};
                *(float2*)(dst + nf * 8) = o;
            }
        }
    }
}

// ---------------------------------------------------------------------------
// K3a: per-chunk products. grid (96 bh, 4), block 1024 = (16 chunks x 64 m).
// ---------------------------------------------------------------------------
__global__ void __launch_bounds__(1024) k_scan_a() {
    const int bh = blockIdx.x;
    const int b = bh / NH, h = bh % NH;
    const int ci = blockIdx.y * 16 + (threadIdx.x >> 6);   // 0..63
    const int m = threadIdx.x & 63;
    const size_t base = (size_t)b * T_SZ * HM + h * NS + m;
    const int t0 = ci * 64;
    float prod = 1.f;
#pragma unroll 1
    for (int tb = 0; tb < 64; tb += 8) {
        float wv[8];
#pragma unroll
        for (int i = 0; i < 8; i++) wv[i] = g_w[base + (size_t)(t0 + tb + i) * HM];
#pragma unroll
        for (int i = 0; i < 8; i++) prod *= (1.f - ALPHAF * wv[i]);
    }
    g_cp[(bh * 64 + ci) * 64 + m] = prod;
}

// ---------------------------------------------------------------------------
// K3b: suffix combine across 64 chunks; g_cp -> exclusive-suffix offsets.
// ---------------------------------------------------------------------------
__global__ void __launch_bounds__(64) k_scan_b() {
    const int bh = blockIdx.x;
    const int m = threadIdx.x;
    float run = 1.f;
    for (int ci = 63; ci >= 0; ci--) {
        int idx = (bh * 64 + ci) * 64 + m;
        float cp = g_cp[idx];
        g_cp[idx] = run;
        run *= cp;
    }
    g_res[bh * NS + m] = run;
}

// ---------------------------------------------------------------------------
// K3c: apply: w_eff[t] = a*w[t] * suffix_exc, in place.
// ---------------------------------------------------------------------------
__global__ void __launch_bounds__(1024) k_scan_c() {
    const int bh = blockIdx.x;
    const int b = bh / NH, h = bh % NH;
    const int ci = blockIdx.y * 16 + (threadIdx.x >> 6);
    const int m = threadIdx.x & 63;
    const size_t base = (size_t)b * T_SZ * HM + h * NS + m;
    const int t0 = ci * 64;
    float run = g_cp[(bh * 64 + ci) * 64 + m];
#pragma unroll 1
    for (int tb = 63; tb >= 0; tb -= 8) {
        float wv[8];
        size_t idx[8];
#pragma unroll
        for (int i = 0; i < 8; i++) {
            idx[i] = base + (size_t)(t0 + tb - i) * HM;
            wv[i] = g_w[idx[i]];
        }
#pragma unroll
        for (int i = 0; i < 8; i++) {
            g_w[idx[i]] = ALPHAF * wv[i] * run;
            run *= (1.f - ALPHAF * wv[i]);
        }
    }
}

// ---------------------------------------------------------------------------
// K4a: out init with s0 * residual
// ---------------------------------------------------------------------------
__global__ void k_init_out(const float* __restrict__ s0, float* __restrict__ out) {
    int idx = blockIdx.x * blockDim.x + threadIdx.x;
    if (idx >= B_SZ * NS * D_SZ) return;
    int dj = idx % D_SZ;
    int m  = (idx / D_SZ) % NS;
    int b  = idx / (D_SZ * NS);
    int h  = dj / HD;
    out[idx] = s0[(size_t)m * D_SZ + dj] * g_res[(b * NH + h) * NS + m];
}

// ---------------------------------------------------------------------------
// K4b: out[b, m, h*64+j] += sum_t w_eff[b,h,t,m] * H[b,t,h*64+j]
// ---------------------------------------------------------------------------
__global__ void __launch_bounds__(256) k_accum(const float* __restrict__ H,
                                               float* __restrict__ out) {
    const int bh = blockIdx.x;
    const int b = bh / NH, h = bh % NH;
    const int tstart = blockIdx.y * (T_SZ / 8);

    __shared__ float sw[8][64];
    __shared__ float sh[8][64];

    const int tid = threadIdx.x;
    const int tm = tid >> 4;
    const int tj = tid & 15;

    float acc[4][4];
#pragma unroll
    for (int i = 0; i < 4; i++)
#pragma unroll
        for (int j = 0; j < 4; j++) acc[i][j] = 0.f;

    for (int tt = 0; tt < T_SZ / 8; tt += 8) {
        __syncthreads();
#pragma unroll
        for (int l = tid; l < 512; l += 256) {
            int lt = l >> 6, lm = l & 63;
            int t = tstart + tt + lt;
            size_t bt = (size_t)b * T_SZ + t;
            sw[lt][lm] = g_w[bt * HM + h * NS + lm];
            sh[lt][lm] = H[bt * D_SZ + h * HD + lm];
        }
        __syncthreads();
#pragma unroll
        for (int lt = 0; lt < 8; lt++) {
            float4 a4 = *(const float4*)&sw[lt][tm * 4];
            float4 b4 = *(const float4*)&sh[lt][tj * 4];
            float av[4] = {a4.x, a4.y, a4.z, a4.w};
            float bv[4] = {b4.x, b4.y, b4.z, b4.w};
#pragma unroll
            for (int i = 0; i < 4; i++)
#pragma unroll
                for (int j = 0; j < 4; j++) acc[i][j] = fmaf(av[i], bv[j], acc[i][j]);
        }
    }

#pragma unroll
    for (int i = 0; i < 4; i++) {
        int m = tm * 4 + i;
        float* dst = out + ((size_t)b * NS + m) * D_SZ + h * HD + tj * 4;
#pragma unroll
        for (int j = 0; j < 4; j++) atomicAdd(dst + j, acc[i][j]);
    }
}

// ---------------------------------------------------------------------------
extern "C" void kernel_launch(void* const* d_in, const int* in_sizes, int n_in,
                              void* d_out, int out_size) {
    const float* H     = (const float*)d_in[0];   // [8, 4096, 768]
    const float* proto = (const float*)d_in[1];   // [64, 768]
    const float* W     = (const float*)d_in[2];   // [768, 768]
    const float* s0    = (const float*)d_in[3];   // [1, 64, 768]
    float* out = (float*)d_out;                   // [8, 64, 768]
    (void)in_sizes; (void)n_in; (void)out_size;

    cudaFuncSetAttribute(k_gemm_mma, cudaFuncAttributeMaxDynamicSharedMemorySize,
                         GEMM_SMEM);

    k_build_C<<<(HM * D_SZ + 255) / 256, 256>>>(W, proto);

    dim3 g1(HM / 128, BT / 128);   // (6, 256)
    k_gemm_mma<<<g1, 256, GEMM_SMEM>>>(H);

    dim3 g3(B_SZ * NH, 4);
    k_scan_a<<<g3, 1024>>>();
    k_scan_b<<<B_SZ * NH, 64>>>();
    k_scan_c<<<g3, 1024>>>();

    k_init_out<<<(B_SZ * NS * D_SZ + 255) / 256, 256>>>(s0, out);

    dim3 g4(B_SZ * NH, 8);
    k_accum<<<g4, 256>>>(H, out);
}

// round 7
// speedup vs baseline: 2.5767x; 1.0717x over previous
#include <cuda_runtime.h>
#include <cuda_bf16.h>
#include <cstdint>

// Problem constants
#define B_SZ   8
#define T_SZ   4096
#define D_SZ   768
#define NH     12
#define HD     64
#define NS     64
#define ALPHAF 0.1f
#define BT     (B_SZ * T_SZ)   // 32768
#define HM     (NH * NS)       // 768

// Scratch (static device globals: allocation APIs are forbidden)
__device__ __nv_bfloat16 g_Ah[(size_t)BT * D_SZ];   // H hi, 48MB
__device__ __nv_bfloat16 g_Al[(size_t)BT * D_SZ];   // H lo, 48MB
__device__ __nv_bfloat16 g_Ch[HM * D_SZ];           // C hi
__device__ __nv_bfloat16 g_Cl[HM * D_SZ];           // C lo
__device__ float g_w[(size_t)BT * HM];              // softmax w (fp32), 96MB
__device__ __nv_bfloat16 g_wh[(size_t)BT * HM];     // w_eff hi, 48MB
__device__ __nv_bfloat16 g_wl[(size_t)BT * HM];     // w_eff lo, 48MB
__device__ float g_res[B_SZ * NH * NS];             // total suffix product
__device__ float g_cp[B_SZ * NH * 64 * 64];         // chunk suffix offsets

// ============================ helpers ======================================
__device__ __forceinline__ uint32_t smem_u32(const void* p) {
    uint32_t a;
    asm("{ .reg .u64 t; cvta.to.shared.u64 t, %1; cvt.u32.u64 %0, t; }"
        : "=r"(a) : "l"(p));
    return a;
}
// result = {hi16 = bf16(h), lo16 = bf16(l)}  (memory order: l then h)
__device__ __forceinline__ uint32_t cvt_bf16x2(float h, float l) {
    uint32_t r;
    asm("cvt.rn.bf16x2.f32 %0, %1, %2;" : "=r"(r) : "f"(h), "f"(l));
    return r;
}
__device__ __forceinline__ void ldm_x4(uint32_t* r, uint32_t addr) {
    asm volatile("ldmatrix.sync.aligned.m8n8.x4.shared.b16 {%0,%1,%2,%3}, [%4];"
        : "=r"(r[0]), "=r"(r[1]), "=r"(r[2]), "=r"(r[3]) : "r"(addr));
}
__device__ __forceinline__ void ldm_x4t(uint32_t* r, uint32_t addr) {
    asm volatile("ldmatrix.sync.aligned.m8n8.x4.trans.shared.b16 {%0,%1,%2,%3}, [%4];"
        : "=r"(r[0]), "=r"(r[1]), "=r"(r[2]), "=r"(r[3]) : "r"(addr));
}
__device__ __forceinline__ void mma_bf16(float* d, const uint32_t* a, const uint32_t* b) {
    asm volatile(
        "mma.sync.aligned.m16n8k16.row.col.f32.bf16.bf16.f32 "
        "{%0,%1,%2,%3}, {%4,%5,%6,%7}, {%8,%9}, {%0,%1,%2,%3};"
        : "+f"(d[0]), "+f"(d[1]), "+f"(d[2]), "+f"(d[3])
        : "r"(a[0]), "r"(a[1]), "r"(a[2]), "r"(a[3]), "r"(b[0]), "r"(b[1]));
}
__device__ __forceinline__ void cp16(uint32_t dst, const void* src) {
    asm volatile("cp.async.cg.shared.global [%0], [%1], 16;" :: "r"(dst), "l"(src));
}
#define CP_COMMIT() asm volatile("cp.async.commit_group;" ::: "memory")
#define CP_WAIT(n)  asm volatile("cp.async.wait_group %0;" :: "n"(n) : "memory")

// ---------------------------------------------------------------------------
// K_split: H fp32 -> bf16 hi/lo arrays (one-time).
// ---------------------------------------------------------------------------
__global__ void __launch_bounds__(256) k_split(const float4* __restrict__ H4) {
    size_t i = (size_t)blockIdx.x * 256 + threadIdx.x;   // over BT*768/4
    float4 v = H4[i];
    uint32_t h01 = cvt_bf16x2(v.y, v.x);
    uint32_t h23 = cvt_bf16x2(v.w, v.z);
    float f0 = __uint_as_float(h01 << 16);
    float f1 = __uint_as_float(h01 & 0xFFFF0000u);
    float f2 = __uint_as_float(h23 << 16);
    float f3 = __uint_as_float(h23 & 0xFFFF0000u);
    ((uint2*)g_Ah)[i] = make_uint2(h01, h23);
    ((uint2*)g_Al)[i] = make_uint2(cvt_bf16x2(v.y - f1, v.x - f0),
                                   cvt_bf16x2(v.w - f3, v.z - f2));
}

// ---------------------------------------------------------------------------
// K0: C[h*64+m, d] = (1/8) * sum_j W_tok[h*64+j, d] * proto[m*768 + h*64 + j]
//     emitted directly as bf16 hi/lo.
// ---------------------------------------------------------------------------
__global__ void k_build_C(const float* __restrict__ W, const float* __restrict__ proto) {
    int idx = blockIdx.x * blockDim.x + threadIdx.x;
    if (idx >= HM * D_SZ) return;
    int d  = idx % D_SZ;
    int hm = idx / D_SZ;
    int h = hm / NS, m = hm % NS;
    const float* wcol = W + (size_t)(h * HD) * D_SZ + d;
    const float* prow = proto + (size_t)m * D_SZ + h * HD;
    float acc = 0.f;
#pragma unroll 8
    for (int j = 0; j < HD; j++) acc += wcol[(size_t)j * D_SZ] * prow[j];
    acc *= 0.125f;
    __nv_bfloat16 hi = __float2bfloat16(acc);
    g_Ch[idx] = hi;
    g_Cl[idx] = __float2bfloat16(acc - __bfloat162float(hi));
}

// ---------------------------------------------------------------------------
// K1: mma.sync bf16x3 GEMM (scores) + fused per-head softmax epilogue.
// CTA tile 128x128; 8 warps 4(m)x2(n); warp 32x64 (one full head).
// 4-stage cp.async pipeline, chunks of 32 k, row pitch 80B.
// ---------------------------------------------------------------------------
#define ARR_BYTES   10240                 // 128 * 80
#define STG_BYTES   40960                 // 4 arrays
#define GEMM_SMEM   (4 * STG_BYTES)       // 163840

__global__ void __launch_bounds__(256, 1) k_gemm_mma() {
    extern __shared__ char smem[];
    const uint32_t sbase = smem_u32(smem);
    const int tid = threadIdx.x;
    const int wid = tid >> 5;
    const int lid = tid & 31;
    const int warpM = wid & 3;
    const int warpN = wid >> 2;
    const int m0 = blockIdx.y * 128;
    const int n0 = blockIdx.x * 128;

    auto issue = [&](int kt) {
        const int s = kt & 3;
        const uint32_t sb = sbase + s * STG_BYTES;
        const int koff = kt * 32;
#pragma unroll
        for (int i = 0; i < 8; i++) {
            const int arr = i >> 1;                 // compile-time per i
            const int rem = tid + 256 * (i & 1);
            const int row = rem >> 2;
            const int q   = rem & 3;
            const __nv_bfloat16* src =
                (arr == 0 ? g_Ah + (size_t)(m0 + row) * D_SZ :
                 arr == 1 ? g_Al + (size_t)(m0 + row) * D_SZ :
                 arr == 2 ? g_Ch + (size_t)(n0 + row) * D_SZ :
                            g_Cl + (size_t)(n0 + row) * D_SZ) + koff + q * 8;
            cp16(sb + arr * ARR_BYTES + row * 80 + q * 16, src);
        }
        CP_COMMIT();
    };

    float acc[2][8][4];
#pragma unroll
    for (int mf = 0; mf < 2; mf++)
#pragma unroll
        for (int nf = 0; nf < 8; nf++)
#pragma unroll
            for (int c = 0; c < 4; c++) acc[mf][nf][c] = 0.f;

    const int a_row_add = (lid & 7) + ((lid >> 3) & 1) * 8;
    const int a_k_add   = (lid >> 4) * 16;
    const int b_row_add = (lid & 7) + ((lid >> 4) & 1) * 8;
    const int b_k_add   = ((lid >> 3) & 1) * 16;

    auto domath = [&](int s) {
        const uint32_t stg = sbase + s * STG_BYTES;
#pragma unroll
        for (int ks = 0; ks < 2; ks++) {
            const int kB = ks * 32;
            uint32_t aH[2][4], aL[2][4];
#pragma unroll
            for (int mf = 0; mf < 2; mf++) {
                int row = warpM * 32 + mf * 16 + a_row_add;
                uint32_t addr = stg + (uint32_t)(row * 80 + kB + a_k_add);
                ldm_x4(aH[mf], addr);
                ldm_x4(aL[mf], addr + ARR_BYTES);
            }
            uint32_t bH[4][4], bL[4][4];
#pragma unroll
            for (int nf2 = 0; nf2 < 4; nf2++) {
                int nrow = warpN * 64 + nf2 * 16 + b_row_add;
                uint32_t addr = stg + 2 * ARR_BYTES + (uint32_t)(nrow * 80 + kB + b_k_add);
                ldm_x4(bH[nf2], addr);
                ldm_x4(bL[nf2], addr + ARR_BYTES);
            }
#pragma unroll
            for (int mf = 0; mf < 2; mf++)
#pragma unroll
                for (int nf = 0; nf < 8; nf++) {
                    const uint32_t* bh = &bH[nf >> 1][(nf & 1) * 2];
                    const uint32_t* bl = &bL[nf >> 1][(nf & 1) * 2];
                    mma_bf16(acc[mf][nf], aH[mf], bh);
                    mma_bf16(acc[mf][nf], aH[mf], bl);
                    mma_bf16(acc[mf][nf], aL[mf], bh);
                }
        }
    };

    const int KT = D_SZ / 32;  // 24
    issue(0); issue(1); issue(2);
    for (int kt = 0; kt < KT; kt++) {
        if (kt < KT - 2)       CP_WAIT(2);
        else if (kt == KT - 2) CP_WAIT(1);
        else                   CP_WAIT(0);
        __syncthreads();
        domath(kt & 3);
        if (kt + 3 < KT) issue(kt + 3);
    }

    // Epilogue: softmax per row over this warp's 64-col head, write w (fp32).
    const int colq = (lid & 3) * 2;
#pragma unroll
    for (int mf = 0; mf < 2; mf++) {
#pragma unroll
        for (int half = 0; half < 2; half++) {
            const int row = m0 + warpM * 32 + mf * 16 + (lid >> 2) + half * 8;
            float mx = -3.4e38f;
#pragma unroll
            for (int nf = 0; nf < 8; nf++) {
                mx = fmaxf(mx, acc[mf][nf][half * 2]);
                mx = fmaxf(mx, acc[mf][nf][half * 2 + 1]);
            }
            mx = fmaxf(mx, __shfl_xor_sync(0xFFFFFFFFu, mx, 1));
            mx = fmaxf(mx, __shfl_xor_sync(0xFFFFFFFFu, mx, 2));
            float s = 0.f;
            float ev[8][2];
#pragma unroll
            for (int nf = 0; nf < 8; nf++) {
                ev[nf][0] = __expf(acc[mf][nf][half * 2]     - mx);
                ev[nf][1] = __expf(acc[mf][nf][half * 2 + 1] - mx);
                s += ev[nf][0] + ev[nf][1];
            }
            s += __shfl_xor_sync(0xFFFFFFFFu, s, 1);
            s += __shfl_xor_sync(0xFFFFFFFFu, s, 2);
            const float inv = 1.0f / s;
            float* dst = g_w + (size_t)row * HM + n0 + warpN * 64 + colq;
#pragma unroll
            for (int nf = 0; nf < 8; nf++) {
                float2 o = {ev[nf][0] * inv, ev[nf][1] * inv};
                *(float2*)(dst + nf * 8) = o;
            }
        }
    }
}

// ---------------------------------------------------------------------------
// K3a: per-chunk products. grid (96 bh, 4), block 1024 = (16 chunks x 64 m).
// ---------------------------------------------------------------------------
__global__ void __launch_bounds__(1024) k_scan_a() {
    const int bh = blockIdx.x;
    const int b = bh / NH, h = bh % NH;
    const int ci = blockIdx.y * 16 + (threadIdx.x >> 6);
    const int m = threadIdx.x & 63;
    const size_t base = (size_t)b * T_SZ * HM + h * NS + m;
    const int t0 = ci * 64;
    float prod = 1.f;
#pragma unroll 1
    for (int tb = 0; tb < 64; tb += 8) {
        float wv[8];
#pragma unroll
        for (int i = 0; i < 8; i++) wv[i] = g_w[base + (size_t)(t0 + tb + i) * HM];
#pragma unroll
        for (int i = 0; i < 8; i++) prod *= (1.f - ALPHAF * wv[i]);
    }
    g_cp[(bh * 64 + ci) * 64 + m] = prod;
}

// ---------------------------------------------------------------------------
// K3b: suffix combine across 64 chunks; g_cp -> exclusive-suffix offsets.
// ---------------------------------------------------------------------------
__global__ void __launch_bounds__(64) k_scan_b() {
    const int bh = blockIdx.x;
    const int m = threadIdx.x;
    float run = 1.f;
    for (int ci = 63; ci >= 0; ci--) {
        int idx = (bh * 64 + ci) * 64 + m;
        float cp = g_cp[idx];
        g_cp[idx] = run;
        run *= cp;
    }
    g_res[bh * NS + m] = run;
}

// ---------------------------------------------------------------------------
// K3c: w_eff[t] = a*w[t]*suffix_exc; write bf16 hi/lo for the accum GEMM.
// ---------------------------------------------------------------------------
__global__ void __launch_bounds__(1024) k_scan_c() {
    const int bh = blockIdx.x;
    const int b = bh / NH, h = bh % NH;
    const int ci = blockIdx.y * 16 + (threadIdx.x >> 6);
    const int m = threadIdx.x & 63;
    const size_t base = (size_t)b * T_SZ * HM + h * NS + m;
    const int t0 = ci * 64;
    float run = g_cp[(bh * 64 + ci) * 64 + m];
#pragma unroll 1
    for (int tb = 63; tb >= 0; tb -= 8) {
        float wv[8];
        size_t idx[8];
#pragma unroll
        for (int i = 0; i < 8; i++) {
            idx[i] = base + (size_t)(t0 + tb - i) * HM;
            wv[i] = g_w[idx[i]];
        }
#pragma unroll
        for (int i = 0; i < 8; i++) {
            float we = ALPHAF * wv[i] * run;
            __nv_bfloat16 hi = __float2bfloat16(we);
            g_wh[idx[i]] = hi;
            g_wl[idx[i]] = __float2bfloat16(we - __bfloat162float(hi));
            run *= (1.f - ALPHAF * wv[i]);
        }
    }
}

// ---------------------------------------------------------------------------
// K4a: out init with s0 * residual
// ---------------------------------------------------------------------------
__global__ void k_init_out(const float* __restrict__ s0, float* __restrict__ out) {
    int idx = blockIdx.x * blockDim.x + threadIdx.x;
    if (idx >= B_SZ * NS * D_SZ) return;
    int dj = idx % D_SZ;
    int m  = (idx / D_SZ) % NS;
    int b  = idx / (D_SZ * NS);
    int h  = dj / HD;
    out[idx] = s0[(size_t)m * D_SZ + dj] * g_res[(b * NH + h) * NS + m];
}

// ---------------------------------------------------------------------------
// K4b (mma): out[b, m, h*64+j] += sum_t w_eff[b,h,t,m] * H[b,t,h*64+j]
// Per block: (bh, tsplit of 512). M=64(m) x N=64(j), K chunks of 64.
// Both operands t-major in smem (pitch 144B) -> ldmatrix .trans.
// 8 warps: 4(m=16) x 2(j=32). Double-buffered cp.async. fp32 atomics out.
// ---------------------------------------------------------------------------
#define ACC_ARR  9216       // 64 * 144
#define ACC_STG  36864      // 4 arrays
#define ACC_SMEM 73728      // 2 stages

__global__ void __launch_bounds__(256) k_accum_mma(float* __restrict__ out) {
    extern __shared__ char smem[];
    const uint32_t sbase = smem_u32(smem);
    const int tid = threadIdx.x;
    const int lid = tid & 31;
    const int wid = tid >> 5;
    const int warpM = wid & 3;            // m band of 16
    const int warpN = wid >> 2;           // j band of 32
    const int bh = blockIdx.x;
    const int b = bh / NH, h = bh % NH;
    const int t0 = blockIdx.y * 512;
    const size_t rowbase = ((size_t)b * T_SZ + t0) * (size_t)HM + h * 64;  // HM==D_SZ

    auto issue = [&](int c) {
        const uint32_t sb = sbase + (c & 1) * ACC_STG;
        const int tch = c * 64;
#pragma unroll
        for (int i = 0; i < 8; i++) {
            const int arr = i >> 1;
            const int rem = tid + 256 * (i & 1);
            const int row = rem >> 3;     // 0..63 (t within chunk)
            const int q   = rem & 7;      // 16B piece (64 bf16 per row)
            const size_t so = rowbase + (size_t)(tch + row) * HM + q * 8;
            const __nv_bfloat16* src =
                (arr == 0 ? g_wh : arr == 1 ? g_wl : arr == 2 ? g_Ah : g_Al) + so;
            cp16(sb + arr * ACC_ARR + row * 144 + q * 16, src);
        }
        CP_COMMIT();
    };

    float acc[4][4];
#pragma unroll
    for (int i = 0; i < 4; i++)
#pragma unroll
        for (int j = 0; j < 4; j++) acc[i][j] = 0.f;

    // trans-ldmatrix lane address terms
    const int ar = (lid & 7) + (lid >> 4) * 8;        // A: stored k-row
    const int ab = ((lid >> 3) & 1) * 16;             // A: m byte-half
    const int br = (lid & 7) + ((lid >> 3) & 1) * 8;  // B: stored k-row
    const int bb = (lid >> 4) * 16;                   // B: n byte-half

    issue(0);
    for (int c = 0; c < 8; c++) {
        if (c + 1 < 8) { issue(c + 1); CP_WAIT(1); }
        else           { CP_WAIT(0); }
        __syncthreads();
        const uint32_t sb = sbase + (c & 1) * ACC_STG;
#pragma unroll
        for (int ks = 0; ks < 4; ks++) {
            uint32_t aaddr = sb + (uint32_t)((ks * 16 + ar) * 144 + warpM * 32 + ab);
            uint32_t aH[4], aL[4];
            ldm_x4t(aH, aaddr);
            ldm_x4t(aL, aaddr + ACC_ARR);
            uint32_t baddr = sb + 2 * ACC_ARR +
                             (uint32_t)((ks * 16 + br) * 144 + warpN * 64 + bb);
            uint32_t bH0[4], bH1[4], bL0[4], bL1[4];
            ldm_x4t(bH0, baddr);
            ldm_x4t(bH1, baddr + 32);
            ldm_x4t(bL0, baddr + ACC_ARR);
            ldm_x4t(bL1, baddr + ACC_ARR + 32);
#pragma unroll
            for (int jb = 0; jb < 2; jb++)
#pragma unroll
                for (int nh = 0; nh < 2; nh++) {
                    const int idx = jb * 2 + nh;
                    const uint32_t* bh2 = (jb == 0 ? &bH0[nh * 2] : &bH1[nh * 2]);
                    const uint32_t* bl2 = (jb == 0 ? &bL0[nh * 2] : &bL1[nh * 2]);
                    mma_bf16(acc[idx], aH, bh2);
                    mma_bf16(acc[idx], aH, bl2);
                    mma_bf16(acc[idx], aL, bh2);
                }
        }
        __syncthreads();
    }

    const int mrow = warpM * 16 + (lid >> 2);
#pragma unroll
    for (int idx = 0; idx < 4; idx++) {
        const int j = warpN * 32 + idx * 8 + (lid & 3) * 2;
        float* dst = out + ((size_t)b * NS + mrow) * D_SZ + h * 64 + j;
        atomicAdd(dst,     acc[idx][0]);
        atomicAdd(dst + 1, acc[idx][1]);
        float* dst2 = dst + 8 * D_SZ;
        atomicAdd(dst2,     acc[idx][2]);
        atomicAdd(dst2 + 1, acc[idx][3]);
    }
}

// ---------------------------------------------------------------------------
extern "C" void kernel_launch(void* const* d_in, const int* in_sizes, int n_in,
                              void* d_out, int out_size) {
    const float* H     = (const float*)d_in[0];   // [8, 4096, 768]
    const float* proto = (const float*)d_in[1];   // [64, 768]
    const float* W     = (const float*)d_in[2];   // [768, 768]
    const float* s0    = (const float*)d_in[3];   // [1, 64, 768]
    float* out = (float*)d_out;                   // [8, 64, 768]
    (void)in_sizes; (void)n_in; (void)out_size;

    cudaFuncSetAttribute(k_gemm_mma, cudaFuncAttributeMaxDynamicSharedMemorySize,
                         GEMM_SMEM);
    cudaFuncSetAttribute(k_accum_mma, cudaFuncAttributeMaxDynamicSharedMemorySize,
                         ACC_SMEM);

    k_split<<<(BT * D_SZ / 4) / 256, 256>>>((const float4*)H);
    k_build_C<<<(HM * D_SZ + 255) / 256, 256>>>(W, proto);

    dim3 g1(HM / 128, BT / 128);   // (6, 256)
    k_gemm_mma<<<g1, 256, GEMM_SMEM>>>();

    dim3 g3(B_SZ * NH, 4);
    k_scan_a<<<g3, 1024>>>();
    k_scan_b<<<B_SZ * NH, 64>>>();
    k_scan_c<<<g3, 1024>>>();

    k_init_out<<<(B_SZ * NS * D_SZ + 255) / 256, 256>>>(s0, out);

    dim3 g4(B_SZ * NH, 8);
    k_accum_mma<<<g4, 256, ACC_SMEM>>>(out);
}

// round 8
// speedup vs baseline: 2.6339x; 1.0222x over previous
#include <cuda_runtime.h>
#include <cuda_bf16.h>
#include <cstdint>

// Problem constants
#define B_SZ   8
#define T_SZ   4096
#define D_SZ   768
#define NH     12
#define HD     64
#define NS     64
#define ALPHAF 0.1f
#define BT     (B_SZ * T_SZ)   // 32768
#define HM     (NH * NS)       // 768

// Scratch (static device globals: allocation APIs are forbidden)
__device__ __nv_bfloat16 g_Ah[(size_t)BT * D_SZ];   // H hi, 48MB
__device__ __nv_bfloat16 g_Al[(size_t)BT * D_SZ];   // H lo, 48MB
__device__ __nv_bfloat16 g_Ch[HM * D_SZ];           // C hi
__device__ __nv_bfloat16 g_Cl[HM * D_SZ];           // C lo
__device__ float g_w[(size_t)BT * HM];              // softmax w (fp32), 96MB
__device__ __nv_bfloat16 g_wh[(size_t)BT * HM];     // w_eff hi, 48MB
__device__ __nv_bfloat16 g_wl[(size_t)BT * HM];     // w_eff lo, 48MB
__device__ float g_res[B_SZ * NH * NS];             // total suffix product
__device__ float g_cp[B_SZ * NH * 32 * 64];         // 128-t chunk products/offsets

// ============================ helpers ======================================
__device__ __forceinline__ uint32_t smem_u32(const void* p) {
    uint32_t a;
    asm("{ .reg .u64 t; cvta.to.shared.u64 t, %1; cvt.u32.u64 %0, t; }"
        : "=r"(a) : "l"(p));
    return a;
}
// result = {hi16 = bf16(h), lo16 = bf16(l)}  (memory order: l then h)
__device__ __forceinline__ uint32_t cvt_bf16x2(float h, float l) {
    uint32_t r;
    asm("cvt.rn.bf16x2.f32 %0, %1, %2;" : "=r"(r) : "f"(h), "f"(l));
    return r;
}
__device__ __forceinline__ void ldm_x4(uint32_t* r, uint32_t addr) {
    asm volatile("ldmatrix.sync.aligned.m8n8.x4.shared.b16 {%0,%1,%2,%3}, [%4];"
        : "=r"(r[0]), "=r"(r[1]), "=r"(r[2]), "=r"(r[3]) : "r"(addr));
}
__device__ __forceinline__ void ldm_x4t(uint32_t* r, uint32_t addr) {
    asm volatile("ldmatrix.sync.aligned.m8n8.x4.trans.shared.b16 {%0,%1,%2,%3}, [%4];"
        : "=r"(r[0]), "=r"(r[1]), "=r"(r[2]), "=r"(r[3]) : "r"(addr));
}
__device__ __forceinline__ void mma_bf16(float* d, const uint32_t* a, const uint32_t* b) {
    asm volatile(
        "mma.sync.aligned.m16n8k16.row.col.f32.bf16.bf16.f32 "
        "{%0,%1,%2,%3}, {%4,%5,%6,%7}, {%8,%9}, {%0,%1,%2,%3};"
        : "+f"(d[0]), "+f"(d[1]), "+f"(d[2]), "+f"(d[3])
        : "r"(a[0]), "r"(a[1]), "r"(a[2]), "r"(a[3]), "r"(b[0]), "r"(b[1]));
}
__device__ __forceinline__ void cp16(uint32_t dst, const void* src) {
    asm volatile("cp.async.cg.shared.global [%0], [%1], 16;" :: "r"(dst), "l"(src));
}
#define CP_COMMIT() asm volatile("cp.async.commit_group;" ::: "memory")
#define CP_WAIT(n)  asm volatile("cp.async.wait_group %0;" :: "n"(n) : "memory")

// ---------------------------------------------------------------------------
// K_split: H fp32 -> bf16 hi/lo arrays (one-time).
// ---------------------------------------------------------------------------
__global__ void __launch_bounds__(256) k_split(const float4* __restrict__ H4) {
    size_t i = (size_t)blockIdx.x * 256 + threadIdx.x;   // over BT*768/4
    float4 v = H4[i];
    uint32_t h01 = cvt_bf16x2(v.y, v.x);
    uint32_t h23 = cvt_bf16x2(v.w, v.z);
    float f0 = __uint_as_float(h01 << 16);
    float f1 = __uint_as_float(h01 & 0xFFFF0000u);
    float f2 = __uint_as_float(h23 << 16);
    float f3 = __uint_as_float(h23 & 0xFFFF0000u);
    ((uint2*)g_Ah)[i] = make_uint2(h01, h23);
    ((uint2*)g_Al)[i] = make_uint2(cvt_bf16x2(v.y - f1, v.x - f0),
                                   cvt_bf16x2(v.w - f3, v.z - f2));
}

// ---------------------------------------------------------------------------
// K0: C[h*64+m, d] = (1/8) * sum_j W_tok[h*64+j, d] * proto[m*768 + h*64 + j]
// ---------------------------------------------------------------------------
__global__ void k_build_C(const float* __restrict__ W, const float* __restrict__ proto) {
    int idx = blockIdx.x * blockDim.x + threadIdx.x;
    if (idx >= HM * D_SZ) return;
    int d  = idx % D_SZ;
    int hm = idx / D_SZ;
    int h = hm / NS, m = hm % NS;
    const float* wcol = W + (size_t)(h * HD) * D_SZ + d;
    const float* prow = proto + (size_t)m * D_SZ + h * HD;
    float acc = 0.f;
#pragma unroll 8
    for (int j = 0; j < HD; j++) acc += wcol[(size_t)j * D_SZ] * prow[j];
    acc *= 0.125f;
    __nv_bfloat16 hi = __float2bfloat16(acc);
    g_Ch[idx] = hi;
    g_Cl[idx] = __float2bfloat16(acc - __bfloat162float(hi));
}

// ---------------------------------------------------------------------------
// K1: mma.sync bf16x3 GEMM (scores) + fused softmax + fused 128-t chunk
//     products (feeds the suffix scan directly; k_scan_a eliminated).
// CTA tile 128(bt) x 128(2 heads); 8 warps 4(m)x2(n); warp 32x64 = full head.
// 4-stage cp.async pipeline, k-chunks of 32, row pitch 80B.
// ---------------------------------------------------------------------------
#define ARR_BYTES   10240                 // 128 * 80
#define STG_BYTES   40960                 // 4 arrays
#define GEMM_SMEM   (4 * STG_BYTES)       // 163840

__global__ void __launch_bounds__(256, 1) k_gemm_mma() {
    extern __shared__ char smem[];
    const uint32_t sbase = smem_u32(smem);
    const int tid = threadIdx.x;
    const int wid = tid >> 5;
    const int lid = tid & 31;
    const int warpM = wid & 3;
    const int warpN = wid >> 2;
    const int m0 = blockIdx.y * 128;
    const int n0 = blockIdx.x * 128;

    auto issue = [&](int kt) {
        const int s = kt & 3;
        const uint32_t sb = sbase + s * STG_BYTES;
        const int koff = kt * 32;
#pragma unroll
        for (int i = 0; i < 8; i++) {
            const int arr = i >> 1;
            const int rem = tid + 256 * (i & 1);
            const int row = rem >> 2;
            const int q   = rem & 3;
            const __nv_bfloat16* src =
                (arr == 0 ? g_Ah + (size_t)(m0 + row) * D_SZ :
                 arr == 1 ? g_Al + (size_t)(m0 + row) * D_SZ :
                 arr == 2 ? g_Ch + (size_t)(n0 + row) * D_SZ :
                            g_Cl + (size_t)(n0 + row) * D_SZ) + koff + q * 8;
            cp16(sb + arr * ARR_BYTES + row * 80 + q * 16, src);
        }
        CP_COMMIT();
    };

    float acc[2][8][4];
#pragma unroll
    for (int mf = 0; mf < 2; mf++)
#pragma unroll
        for (int nf = 0; nf < 8; nf++)
#pragma unroll
            for (int c = 0; c < 4; c++) acc[mf][nf][c] = 0.f;

    const int a_row_add = (lid & 7) + ((lid >> 3) & 1) * 8;
    const int a_k_add   = (lid >> 4) * 16;
    const int b_row_add = (lid & 7) + ((lid >> 4) & 1) * 8;
    const int b_k_add   = ((lid >> 3) & 1) * 16;

    auto domath = [&](int s) {
        const uint32_t stg = sbase + s * STG_BYTES;
#pragma unroll
        for (int ks = 0; ks < 2; ks++) {
            const int kB = ks * 32;
            uint32_t aH[2][4], aL[2][4];
#pragma unroll
            for (int mf = 0; mf < 2; mf++) {
                int row = warpM * 32 + mf * 16 + a_row_add;
                uint32_t addr = stg + (uint32_t)(row * 80 + kB + a_k_add);
                ldm_x4(aH[mf], addr);
                ldm_x4(aL[mf], addr + ARR_BYTES);
            }
            uint32_t bH[4][4], bL[4][4];
#pragma unroll
            for (int nf2 = 0; nf2 < 4; nf2++) {
                int nrow = warpN * 64 + nf2 * 16 + b_row_add;
                uint32_t addr = stg + 2 * ARR_BYTES + (uint32_t)(nrow * 80 + kB + b_k_add);
                ldm_x4(bH[nf2], addr);
                ldm_x4(bL[nf2], addr + ARR_BYTES);
            }
#pragma unroll
            for (int mf = 0; mf < 2; mf++)
#pragma unroll
                for (int nf = 0; nf < 8; nf++) {
                    const uint32_t* bh = &bH[nf >> 1][(nf & 1) * 2];
                    const uint32_t* bl = &bL[nf >> 1][(nf & 1) * 2];
                    mma_bf16(acc[mf][nf], aH[mf], bh);
                    mma_bf16(acc[mf][nf], aH[mf], bl);
                    mma_bf16(acc[mf][nf], aL[mf], bh);
                }
        }
    };

    const int KT = D_SZ / 32;  // 24
    issue(0); issue(1); issue(2);
    for (int kt = 0; kt < KT; kt++) {
        if (kt < KT - 2)       CP_WAIT(2);
        else if (kt == KT - 2) CP_WAIT(1);
        else                   CP_WAIT(0);
        __syncthreads();
        domath(kt & 3);
        if (kt + 3 < KT) issue(kt + 3);
    }

    // Epilogue: softmax per row over this warp's 64-col head; write w (fp32);
    // accumulate per-lane running products of (1 - alpha*w) for the chunk.
    const int colq = (lid & 3) * 2;
    float pl[8][2];
#pragma unroll
    for (int nf = 0; nf < 8; nf++) { pl[nf][0] = 1.f; pl[nf][1] = 1.f; }

#pragma unroll
    for (int mf = 0; mf < 2; mf++) {
#pragma unroll
        for (int half = 0; half < 2; half++) {
            const int row = m0 + warpM * 32 + mf * 16 + (lid >> 2) + half * 8;
            float mx = -3.4e38f;
#pragma unroll
            for (int nf = 0; nf < 8; nf++) {
                mx = fmaxf(mx, acc[mf][nf][half * 2]);
                mx = fmaxf(mx, acc[mf][nf][half * 2 + 1]);
            }
            mx = fmaxf(mx, __shfl_xor_sync(0xFFFFFFFFu, mx, 1));
            mx = fmaxf(mx, __shfl_xor_sync(0xFFFFFFFFu, mx, 2));
            float s = 0.f;
            float ev[8][2];
#pragma unroll
            for (int nf = 0; nf < 8; nf++) {
                ev[nf][0] = __expf(acc[mf][nf][half * 2]     - mx);
                ev[nf][1] = __expf(acc[mf][nf][half * 2 + 1] - mx);
                s += ev[nf][0] + ev[nf][1];
            }
            s += __shfl_xor_sync(0xFFFFFFFFu, s, 1);
            s += __shfl_xor_sync(0xFFFFFFFFu, s, 2);
            const float inv = 1.0f / s;
            float* dst = g_w + (size_t)row * HM + n0 + warpN * 64 + colq;
#pragma unroll
            for (int nf = 0; nf < 8; nf++) {
                float w0 = ev[nf][0] * inv;
                float w1 = ev[nf][1] * inv;
                float2 o = {w0, w1};
                *(float2*)(dst + nf * 8) = o;
                pl[nf][0] *= fmaf(-ALPHAF, w0, 1.f);
                pl[nf][1] *= fmaf(-ALPHAF, w1, 1.f);
            }
        }
    }

    // Combine products across the 8 lanes sharing the same columns (rows).
#pragma unroll
    for (int off = 4; off <= 16; off <<= 1)
#pragma unroll
        for (int nf = 0; nf < 8; nf++) {
            pl[nf][0] *= __shfl_xor_sync(0xFFFFFFFFu, pl[nf][0], off);
            pl[nf][1] *= __shfl_xor_sync(0xFFFFFFFFu, pl[nf][1], off);
        }

    __syncthreads();                       // all domath smem reads done
    float* cpw = (float*)smem;             // [warpN][warpM][64]
    if ((lid >> 2) == 0) {
#pragma unroll
        for (int nf = 0; nf < 8; nf++) {
            cpw[(warpN * 4 + warpM) * 64 + colq + nf * 8]     = pl[nf][0];
            cpw[(warpN * 4 + warpM) * 64 + colq + nf * 8 + 1] = pl[nf][1];
        }
    }
    __syncthreads();
    if (tid < 128) {
        const int wN = tid >> 6, col = tid & 63;
        float p = cpw[(wN * 4 + 0) * 64 + col] * cpw[(wN * 4 + 1) * 64 + col]
                * cpw[(wN * 4 + 2) * 64 + col] * cpw[(wN * 4 + 3) * 64 + col];
        const int b   = m0 >> 12;
        const int tch = (m0 & 4095) >> 7;          // 0..31
        const int head = (n0 >> 6) + wN;
        g_cp[((b * NH + head) * 32 + tch) * 64 + col] = p;
    }
}

// ---------------------------------------------------------------------------
// K3b: suffix combine across 32 chunks; g_cp -> exclusive-suffix offsets.
// ---------------------------------------------------------------------------
__global__ void __launch_bounds__(64) k_scan_b() {
    const int bh = blockIdx.x;
    const int m = threadIdx.x;
    float run = 1.f;
    for (int ci = 31; ci >= 0; ci--) {
        int idx = (bh * 32 + ci) * 64 + m;
        float cp = g_cp[idx];
        g_cp[idx] = run;
        run *= cp;
    }
    g_res[bh * NS + m] = run;
}

// ---------------------------------------------------------------------------
// K3c: w_eff[t] = a*w[t]*suffix_exc; write bf16 hi/lo. 128-t chunks.
// grid (96, 2), block 1024 = (16 chunks x 64 m).
// ---------------------------------------------------------------------------
__global__ void __launch_bounds__(1024) k_scan_c() {
    const int bh = blockIdx.x;
    const int b = bh / NH, h = bh % NH;
    const int ci = blockIdx.y * 16 + (threadIdx.x >> 6);   // 0..31
    const int m = threadIdx.x & 63;
    const size_t base = (size_t)b * T_SZ * HM + h * NS + m;
    const int t0 = ci * 128;
    float run = g_cp[(bh * 32 + ci) * 64 + m];
#pragma unroll 1
    for (int tb = 127; tb >= 0; tb -= 8) {
        float wv[8];
        size_t idx[8];
#pragma unroll
        for (int i = 0; i < 8; i++) {
            idx[i] = base + (size_t)(t0 + tb - i) * HM;
            wv[i] = g_w[idx[i]];
        }
#pragma unroll
        for (int i = 0; i < 8; i++) {
            float we = ALPHAF * wv[i] * run;
            __nv_bfloat16 hi = __float2bfloat16(we);
            g_wh[idx[i]] = hi;
            g_wl[idx[i]] = __float2bfloat16(we - __bfloat162float(hi));
            run *= (1.f - ALPHAF * wv[i]);
        }
    }
}

// ---------------------------------------------------------------------------
// K4a: out init with s0 * residual
// ---------------------------------------------------------------------------
__global__ void k_init_out(const float* __restrict__ s0, float* __restrict__ out) {
    int idx = blockIdx.x * blockDim.x + threadIdx.x;
    if (idx >= B_SZ * NS * D_SZ) return;
    int dj = idx % D_SZ;
    int m  = (idx / D_SZ) % NS;
    int b  = idx / (D_SZ * NS);
    int h  = dj / HD;
    out[idx] = s0[(size_t)m * D_SZ + dj] * g_res[(b * NH + h) * NS + m];
}

// ---------------------------------------------------------------------------
// K4b (mma): out[b, m, h*64+j] += sum_t w_eff[b,h,t,m] * H[b,t,h*64+j]
// Per block: (bh, tsplit of 512). M=64(m) x N=64(j), K chunks of 64.
// Both operands t-major in smem (pitch 144B) -> ldmatrix .trans.
// ---------------------------------------------------------------------------
#define ACC_ARR  9216       // 64 * 144
#define ACC_STG  36864      // 4 arrays
#define ACC_SMEM 73728      // 2 stages

__global__ void __launch_bounds__(256) k_accum_mma(float* __restrict__ out) {
    extern __shared__ char smem[];
    const uint32_t sbase = smem_u32(smem);
    const int tid = threadIdx.x;
    const int lid = tid & 31;
    const int wid = tid >> 5;
    const int warpM = wid & 3;
    const int warpN = wid >> 2;
    const int bh = blockIdx.x;
    const int b = bh / NH, h = bh % NH;
    const int t0 = blockIdx.y * 512;
    const size_t rowbase = ((size_t)b * T_SZ + t0) * (size_t)HM + h * 64;

    auto issue = [&](int c) {
        const uint32_t sb = sbase + (c & 1) * ACC_STG;
        const int tch = c * 64;
#pragma unroll
        for (int i = 0; i < 8; i++) {
            const int arr = i >> 1;
            const int rem = tid + 256 * (i & 1);
            const int row = rem >> 3;
            const int q   = rem & 7;
            const size_t so = rowbase + (size_t)(tch + row) * HM + q * 8;
            const __nv_bfloat16* src =
                (arr == 0 ? g_wh : arr == 1 ? g_wl : arr == 2 ? g_Ah : g_Al) + so;
            cp16(sb + arr * ACC_ARR + row * 144 + q * 16, src);
        }
        CP_COMMIT();
    };

    float acc[4][4];
#pragma unroll
    for (int i = 0; i < 4; i++)
#pragma unroll
        for (int j = 0; j < 4; j++) acc[i][j] = 0.f;

    const int ar = (lid & 7) + (lid >> 4) * 8;
    const int ab = ((lid >> 3) & 1) * 16;
    const int br = (lid & 7) + ((lid >> 3) & 1) * 8;
    const int bb = (lid >> 4) * 16;

    issue(0);
    for (int c = 0; c < 8; c++) {
        if (c + 1 < 8) { issue(c + 1); CP_WAIT(1); }
        else           { CP_WAIT(0); }
        __syncthreads();
        const uint32_t sb = sbase + (c & 1) * ACC_STG;
#pragma unroll
        for (int ks = 0; ks < 4; ks++) {
            uint32_t aaddr = sb + (uint32_t)((ks * 16 + ar) * 144 + warpM * 32 + ab);
            uint32_t aH[4], aL[4];
            ldm_x4t(aH, aaddr);
            ldm_x4t(aL, aaddr + ACC_ARR);
            uint32_t baddr = sb + 2 * ACC_ARR +
                             (uint32_t)((ks * 16 + br) * 144 + warpN * 64 + bb);
            uint32_t bH0[4], bH1[4], bL0[4], bL1[4];
            ldm_x4t(bH0, baddr);
            ldm_x4t(bH1, baddr + 32);
            ldm_x4t(bL0, baddr + ACC_ARR);
            ldm_x4t(bL1, baddr + ACC_ARR + 32);
#pragma unroll
            for (int jb = 0; jb < 2; jb++)
#pragma unroll
                for (int nh = 0; nh < 2; nh++) {
                    const int idx = jb * 2 + nh;
                    const uint32_t* bh2 = (jb == 0 ? &bH0[nh * 2] : &bH1[nh * 2]);
                    const uint32_t* bl2 = (jb == 0 ? &bL0[nh * 2] : &bL1[nh * 2]);
                    mma_bf16(acc[idx], aH, bh2);
                    mma_bf16(acc[idx], aH, bl2);
                    mma_bf16(acc[idx], aL, bh2);
                }
        }
        __syncthreads();
    }

    const int mrow = warpM * 16 + (lid >> 2);
#pragma unroll
    for (int idx = 0; idx < 4; idx++) {
        const int j = warpN * 32 + idx * 8 + (lid & 3) * 2;
        float* dst = out + ((size_t)b * NS + mrow) * D_SZ + h * 64 + j;
        atomicAdd(dst,     acc[idx][0]);
        atomicAdd(dst + 1, acc[idx][1]);
        float* dst2 = dst + 8 * D_SZ;
        atomicAdd(dst2,     acc[idx][2]);
        atomicAdd(dst2 + 1, acc[idx][3]);
    }
}

// ---------------------------------------------------------------------------
extern "C" void kernel_launch(void* const* d_in, const int* in_sizes, int n_in,
                              void* d_out, int out_size) {
    const float* H     = (const float*)d_in[0];   // [8, 4096, 768]
    const float* proto = (const float*)d_in[1];   // [64, 768]
    const float* W     = (const float*)d_in[2];   // [768, 768]
    const float* s0    = (const float*)d_in[3];   // [1, 64, 768]
    float* out = (float*)d_out;                   // [8, 64, 768]
    (void)in_sizes; (void)n_in; (void)out_size;

    cudaFuncSetAttribute(k_gemm_mma, cudaFuncAttributeMaxDynamicSharedMemorySize,
                         GEMM_SMEM);
    cudaFuncSetAttribute(k_accum_mma, cudaFuncAttributeMaxDynamicSharedMemorySize,
                         ACC_SMEM);

    k_split<<<(BT * D_SZ / 4) / 256, 256>>>((const float4*)H);
    k_build_C<<<(HM * D_SZ + 255) / 256, 256>>>(W, proto);

    dim3 g1(HM / 128, BT / 128);   // (6, 256)
    k_gemm_mma<<<g1, 256, GEMM_SMEM>>>();

    k_scan_b<<<B_SZ * NH, 64>>>();
    dim3 g3(B_SZ * NH, 2);
    k_scan_c<<<g3, 1024>>>();

    k_init_out<<<(B_SZ * NS * D_SZ + 255) / 256, 256>>>(s0, out);

    dim3 g4(B_SZ * NH, 8);
    k_accum_mma<<<g4, 256, ACC_SMEM>>>(out);
}

// round 10
// speedup vs baseline: 2.6664x; 1.0124x over previous
#include <cuda_runtime.h>
#include <cuda_bf16.h>
#include <cstdint>

// Problem constants
#define B_SZ   8
#define T_SZ   4096
#define D_SZ   768
#define NH     12
#define HD     64
#define NS     64
#define ALPHAF 0.1f
#define BT     (B_SZ * T_SZ)   // 32768
#define HM     (NH * NS)       // 768

// Scratch (static device globals: allocation APIs are forbidden)
__device__ __nv_bfloat16 g_Ah[(size_t)BT * D_SZ];   // H hi, 48MB
__device__ __nv_bfloat16 g_Al[(size_t)BT * D_SZ];   // H lo, 48MB
__device__ __nv_bfloat16 g_Ch[HM * D_SZ];           // C hi
__device__ __nv_bfloat16 g_Cl[HM * D_SZ];           // C lo
__device__ float g_w[(size_t)BT * HM];              // softmax w (fp32), 96MB
__device__ __nv_bfloat16 g_wh[(size_t)BT * HM];     // w_eff hi, 48MB
__device__ __nv_bfloat16 g_wl[(size_t)BT * HM];     // w_eff lo, 48MB
__device__ float g_res[B_SZ * NH * NS];             // total suffix product
__device__ float g_cp[B_SZ * NH * 128 * 64];        // 32-t chunk products/offsets

// ============================ helpers ======================================
__device__ __forceinline__ uint32_t smem_u32(const void* p) {
    uint32_t a;
    asm("{ .reg .u64 t; cvta.to.shared.u64 t, %1; cvt.u32.u64 %0, t; }"
        : "=r"(a) : "l"(p));
    return a;
}
// result = {hi16 = bf16(h), lo16 = bf16(l)}  (memory order: l then h)
__device__ __forceinline__ uint32_t cvt_bf16x2(float h, float l) {
    uint32_t r;
    asm("cvt.rn.bf16x2.f32 %0, %1, %2;" : "=r"(r) : "f"(h), "f"(l));
    return r;
}
__device__ __forceinline__ void ldm_x4(uint32_t* r, uint32_t addr) {
    asm volatile("ldmatrix.sync.aligned.m8n8.x4.shared.b16 {%0,%1,%2,%3}, [%4];"
        : "=r"(r[0]), "=r"(r[1]), "=r"(r[2]), "=r"(r[3]) : "r"(addr));
}
__device__ __forceinline__ void ldm_x4t(uint32_t* r, uint32_t addr) {
    asm volatile("ldmatrix.sync.aligned.m8n8.x4.trans.shared.b16 {%0,%1,%2,%3}, [%4];"
        : "=r"(r[0]), "=r"(r[1]), "=r"(r[2]), "=r"(r[3]) : "r"(addr));
}
__device__ __forceinline__ void mma_bf16(float* d, const uint32_t* a, const uint32_t* b) {
    asm volatile(
        "mma.sync.aligned.m16n8k16.row.col.f32.bf16.bf16.f32 "
        "{%0,%1,%2,%3}, {%4,%5,%6,%7}, {%8,%9}, {%0,%1,%2,%3};"
        : "+f"(d[0]), "+f"(d[1]), "+f"(d[2]), "+f"(d[3])
        : "r"(a[0]), "r"(a[1]), "r"(a[2]), "r"(a[3]), "r"(b[0]), "r"(b[1]));
}
__device__ __forceinline__ void cp16(uint32_t dst, const void* src) {
    asm volatile("cp.async.cg.shared.global [%0], [%1], 16;" :: "r"(dst), "l"(src));
}
#define CP_COMMIT() asm volatile("cp.async.commit_group;" ::: "memory")
#define CP_WAIT(n)  asm volatile("cp.async.wait_group %0;" :: "n"(n) : "memory")

// ---------------------------------------------------------------------------
// K_split: H fp32 -> bf16 hi/lo arrays (one-time).
// ---------------------------------------------------------------------------
__global__ void __launch_bounds__(256) k_split(const float4* __restrict__ H4) {
    size_t i = (size_t)blockIdx.x * 256 + threadIdx.x;   // over BT*768/4
    float4 v = H4[i];
    uint32_t h01 = cvt_bf16x2(v.y, v.x);
    uint32_t h23 = cvt_bf16x2(v.w, v.z);
    float f0 = __uint_as_float(h01 << 16);
    float f1 = __uint_as_float(h01 & 0xFFFF0000u);
    float f2 = __uint_as_float(h23 << 16);
    float f3 = __uint_as_float(h23 & 0xFFFF0000u);
    ((uint2*)g_Ah)[i] = make_uint2(h01, h23);
    ((uint2*)g_Al)[i] = make_uint2(cvt_bf16x2(v.y - f1, v.x - f0),
                                   cvt_bf16x2(v.w - f3, v.z - f2));
}

// ---------------------------------------------------------------------------
// K0: C[h*64+m, d] = (1/8) * sum_j W_tok[h*64+j, d] * proto[m*768 + h*64 + j]
// ---------------------------------------------------------------------------
__global__ void k_build_C(const float* __restrict__ W, const float* __restrict__ proto) {
    int idx = blockIdx.x * blockDim.x + threadIdx.x;
    if (idx >= HM * D_SZ) return;
    int d  = idx % D_SZ;
    int hm = idx / D_SZ;
    int h = hm / NS, m = hm % NS;
    const float* wcol = W + (size_t)(h * HD) * D_SZ + d;
    const float* prow = proto + (size_t)m * D_SZ + h * HD;
    float acc = 0.f;
#pragma unroll 8
    for (int j = 0; j < HD; j++) acc += wcol[(size_t)j * D_SZ] * prow[j];
    acc *= 0.125f;
    __nv_bfloat16 hi = __float2bfloat16(acc);
    g_Ch[idx] = hi;
    g_Cl[idx] = __float2bfloat16(acc - __bfloat162float(hi));
}

// ---------------------------------------------------------------------------
// K1: mma.sync bf16x3 GEMM (scores) + fused softmax + fused 32-t band
//     products. 2-stage cp.async double buffer, 2 CTAs/SM.
// CTA tile 128(bt) x 128(2 heads); 8 warps 4(m)x2(n); warp 32x64 = full head.
// ---------------------------------------------------------------------------
#define ARR_BYTES   10240                 // 128 * 80
#define STG_BYTES   40960                 // 4 arrays
#define GEMM_SMEM   (2 * STG_BYTES)       // 81920 -> 2 CTAs/SM

__global__ void __launch_bounds__(256, 2) k_gemm_mma() {
    extern __shared__ char smem[];
    const uint32_t sbase = smem_u32(smem);
    const int tid = threadIdx.x;
    const int wid = tid >> 5;
    const int lid = tid & 31;
    const int warpM = wid & 3;
    const int warpN = wid >> 2;
    const int m0 = blockIdx.y * 128;
    const int n0 = blockIdx.x * 128;

    auto issue = [&](int kt) {
        const uint32_t sb = sbase + (kt & 1) * STG_BYTES;
        const int koff = kt * 32;
#pragma unroll
        for (int i = 0; i < 8; i++) {
            const int arr = i >> 1;
            const int rem = tid + 256 * (i & 1);
            const int row = rem >> 2;
            const int q   = rem & 3;
            const __nv_bfloat16* src =
                (arr == 0 ? g_Ah + (size_t)(m0 + row) * D_SZ :
                 arr == 1 ? g_Al + (size_t)(m0 + row) * D_SZ :
                 arr == 2 ? g_Ch + (size_t)(n0 + row) * D_SZ :
                            g_Cl + (size_t)(n0 + row) * D_SZ) + koff + q * 8;
            cp16(sb + arr * ARR_BYTES + row * 80 + q * 16, src);
        }
        CP_COMMIT();
    };

    float acc[2][8][4];
#pragma unroll
    for (int mf = 0; mf < 2; mf++)
#pragma unroll
        for (int nf = 0; nf < 8; nf++)
#pragma unroll
            for (int c = 0; c < 4; c++) acc[mf][nf][c] = 0.f;

    const int a_row_add = (lid & 7) + ((lid >> 3) & 1) * 8;
    const int a_k_add   = (lid >> 4) * 16;
    const int b_row_add = (lid & 7) + ((lid >> 4) & 1) * 8;
    const int b_k_add   = ((lid >> 3) & 1) * 16;

    auto domath = [&](int s) {
        const uint32_t stg = sbase + s * STG_BYTES;
#pragma unroll
        for (int ks = 0; ks < 2; ks++) {
            const int kB = ks * 32;
            uint32_t aH[2][4], aL[2][4];
#pragma unroll
            for (int mf = 0; mf < 2; mf++) {
                int row = warpM * 32 + mf * 16 + a_row_add;
                uint32_t addr = stg + (uint32_t)(row * 80 + kB + a_k_add);
                ldm_x4(aH[mf], addr);
                ldm_x4(aL[mf], addr + ARR_BYTES);
            }
#pragma unroll
            for (int nf2 = 0; nf2 < 4; nf2++) {
                int nrow = warpN * 64 + nf2 * 16 + b_row_add;
                uint32_t addr = stg + 2 * ARR_BYTES + (uint32_t)(nrow * 80 + kB + b_k_add);
                uint32_t bH[4], bL[4];
                ldm_x4(bH, addr);
                ldm_x4(bL, addr + ARR_BYTES);
#pragma unroll
                for (int mf = 0; mf < 2; mf++)
#pragma unroll
                    for (int nh = 0; nh < 2; nh++) {
                        const int nf = nf2 * 2 + nh;
                        mma_bf16(acc[mf][nf], aH[mf], &bH[nh * 2]);
                        mma_bf16(acc[mf][nf], aH[mf], &bL[nh * 2]);
                        mma_bf16(acc[mf][nf], aL[mf], &bH[nh * 2]);
                    }
            }
        }
    };

    const int KT = D_SZ / 32;  // 24
    issue(0);
    for (int kt = 0; kt < KT; kt++) {
        if (kt + 1 < KT) { issue(kt + 1); CP_WAIT(1); }
        else             { CP_WAIT(0); }
        __syncthreads();
        domath(kt & 1);
        __syncthreads();
    }

    // Epilogue: softmax per row over this warp's 64-col head; write w (fp32);
    // accumulate per-lane products of (1 - alpha*w) over this warp's 32 rows.
    const int colq = (lid & 3) * 2;
    float pl[8][2];
#pragma unroll
    for (int nf = 0; nf < 8; nf++) { pl[nf][0] = 1.f; pl[nf][1] = 1.f; }

#pragma unroll
    for (int mf = 0; mf < 2; mf++) {
#pragma unroll
        for (int half = 0; half < 2; half++) {
            const int row = m0 + warpM * 32 + mf * 16 + (lid >> 2) + half * 8;
            float mx = -3.4e38f;
#pragma unroll
            for (int nf = 0; nf < 8; nf++) {
                mx = fmaxf(mx, acc[mf][nf][half * 2]);
                mx = fmaxf(mx, acc[mf][nf][half * 2 + 1]);
            }
            mx = fmaxf(mx, __shfl_xor_sync(0xFFFFFFFFu, mx, 1));
            mx = fmaxf(mx, __shfl_xor_sync(0xFFFFFFFFu, mx, 2));
            float s = 0.f;
            float ev[8][2];
#pragma unroll
            for (int nf = 0; nf < 8; nf++) {
                ev[nf][0] = __expf(acc[mf][nf][half * 2]     - mx);
                ev[nf][1] = __expf(acc[mf][nf][half * 2 + 1] - mx);
                s += ev[nf][0] + ev[nf][1];
            }
            s += __shfl_xor_sync(0xFFFFFFFFu, s, 1);
            s += __shfl_xor_sync(0xFFFFFFFFu, s, 2);
            const float inv = 1.0f / s;
            float* dst = g_w + (size_t)row * HM + n0 + warpN * 64 + colq;
#pragma unroll
            for (int nf = 0; nf < 8; nf++) {
                float w0 = ev[nf][0] * inv;
                float w1 = ev[nf][1] * inv;
                float2 o = {w0, w1};
                *(float2*)(dst + nf * 8) = o;
                pl[nf][0] *= fmaf(-ALPHAF, w0, 1.f);
                pl[nf][1] *= fmaf(-ALPHAF, w1, 1.f);
            }
        }
    }

    // Combine across the 8 lane-rows sharing the same columns -> band product
    // over this warp's 32 t-rows (sub-chunk). Store directly: no smem needed.
#pragma unroll
    for (int off = 4; off <= 16; off <<= 1)
#pragma unroll
        for (int nf = 0; nf < 8; nf++) {
            pl[nf][0] *= __shfl_xor_sync(0xFFFFFFFFu, pl[nf][0], off);
            pl[nf][1] *= __shfl_xor_sync(0xFFFFFFFFu, pl[nf][1], off);
        }

    if (lid < 4) {
        const int b    = m0 >> 12;
        const int tch  = (m0 & 4095) >> 7;         // 128-t tile index 0..31
        const int sub  = tch * 4 + warpM;          // 32-t chunk index 0..127
        const int head = (n0 >> 6) + warpN;
        float* dst = g_cp + ((size_t)(b * NH + head) * 128 + sub) * 64;
#pragma unroll
        for (int nf = 0; nf < 8; nf++) {
            dst[colq + nf * 8]     = pl[nf][0];
            dst[colq + nf * 8 + 1] = pl[nf][1];
        }
    }
}

// ---------------------------------------------------------------------------
// K3b: suffix combine across 128 chunks; g_cp -> exclusive-suffix offsets.
// ---------------------------------------------------------------------------
__global__ void __launch_bounds__(64) k_scan_b() {
    const int bh = blockIdx.x;
    const int m = threadIdx.x;
    float run = 1.f;
    for (int ci = 127; ci >= 0; ci--) {
        int idx = (bh * 128 + ci) * 64 + m;
        float cp = g_cp[idx];
        g_cp[idx] = run;
        run *= cp;
    }
    g_res[bh * NS + m] = run;
}

// ---------------------------------------------------------------------------
// K3c: w_eff[t] = a*w[t]*suffix_exc; write bf16 hi/lo. 32-t chunks.
// grid (96, 8), block 1024 = (16 chunks x 64 m).
// ---------------------------------------------------------------------------
__global__ void __launch_bounds__(1024) k_scan_c() {
    const int bh = blockIdx.x;
    const int b = bh / NH, h = bh % NH;
    const int ci = blockIdx.y * 16 + (threadIdx.x >> 6);   // 0..127
    const int m = threadIdx.x & 63;
    const size_t base = (size_t)b * T_SZ * HM + h * NS + m;
    const int t0 = ci * 32;
    float run = g_cp[(bh * 128 + ci) * 64 + m];
#pragma unroll 1
    for (int tb = 31; tb >= 0; tb -= 8) {
        float wv[8];
        size_t idx[8];
#pragma unroll
        for (int i = 0; i < 8; i++) {
            idx[i] = base + (size_t)(t0 + tb - i) * HM;
            wv[i] = g_w[idx[i]];
        }
#pragma unroll
        for (int i = 0; i < 8; i++) {
            float we = ALPHAF * wv[i] * run;
            __nv_bfloat16 hi = __float2bfloat16(we);
            g_wh[idx[i]] = hi;
            g_wl[idx[i]] = __float2bfloat16(we - __bfloat162float(hi));
            run *= (1.f - ALPHAF * wv[i]);
        }
    }
}

// ---------------------------------------------------------------------------
// K4a: out init with s0 * residual
// ---------------------------------------------------------------------------
__global__ void k_init_out(const float* __restrict__ s0, float* __restrict__ out) {
    int idx = blockIdx.x * blockDim.x + threadIdx.x;
    if (idx >= B_SZ * NS * D_SZ) return;
    int dj = idx % D_SZ;
    int m  = (idx / D_SZ) % NS;
    int b  = idx / (D_SZ * NS);
    int h  = dj / HD;
    out[idx] = s0[(size_t)m * D_SZ + dj] * g_res[(b * NH + h) * NS + m];
}

// ---------------------------------------------------------------------------
// K4b (mma): out[b, m, h*64+j] += sum_t w_eff[b,h,t,m] * H[b,t,h*64+j]
// Per block: (bh, tsplit of 1024). M=64(m) x N=64(j), K chunks of 64.
// ---------------------------------------------------------------------------
#define ACC_ARR  9216       // 64 * 144
#define ACC_STG  36864      // 4 arrays
#define ACC_SMEM 73728      // 2 stages

__global__ void __launch_bounds__(256, 2) k_accum_mma(float* __restrict__ out) {
    extern __shared__ char smem[];
    const uint32_t sbase = smem_u32(smem);
    const int tid = threadIdx.x;
    const int lid = tid & 31;
    const int wid = tid >> 5;
    const int warpM = wid & 3;
    const int warpN = wid >> 2;
    const int bh = blockIdx.x;
    const int b = bh / NH, h = bh % NH;
    const int t0 = blockIdx.y * 1024;
    const size_t rowbase = ((size_t)b * T_SZ + t0) * (size_t)HM + h * 64;

    auto issue = [&](int c) {
        const uint32_t sb = sbase + (c & 1) * ACC_STG;
        const int tch = c * 64;
#pragma unroll
        for (int i = 0; i < 8; i++) {
            const int arr = i >> 1;
            const int rem = tid + 256 * (i & 1);
            const int row = rem >> 3;
            const int q   = rem & 7;
            const size_t so = rowbase + (size_t)(tch + row) * HM + q * 8;
            const __nv_bfloat16* src =
                (arr == 0 ? g_wh : arr == 1 ? g_wl : arr == 2 ? g_Ah : g_Al) + so;
            cp16(sb + arr * ACC_ARR + row * 144 + q * 16, src);
        }
        CP_COMMIT();
    };

    float acc[4][4];
#pragma unroll
    for (int i = 0; i < 4; i++)
#pragma unroll
        for (int j = 0; j < 4; j++) acc[i][j] = 0.f;

    const int ar = (lid & 7) + (lid >> 4) * 8;
    const int ab = ((lid >> 3) & 1) * 16;
    const int br = (lid & 7) + ((lid >> 3) & 1) * 8;
    const int bb = (lid >> 4) * 16;

    issue(0);
    for (int c = 0; c < 16; c++) {
        if (c + 1 < 16) { issue(c + 1); CP_WAIT(1); }
        else            { CP_WAIT(0); }
        __syncthreads();
        const uint32_t sb = sbase + (c & 1) * ACC_STG;
#pragma unroll
        for (int ks = 0; ks < 4; ks++) {
            uint32_t aaddr = sb + (uint32_t)((ks * 16 + ar) * 144 + warpM * 32 + ab);
            uint32_t aH[4], aL[4];
            ldm_x4t(aH, aaddr);
            ldm_x4t(aL, aaddr + ACC_ARR);
            uint32_t baddr = sb + 2 * ACC_ARR +
                             (uint32_t)((ks * 16 + br) * 144 + warpN * 64 + bb);
#pragma unroll
            for (int jb = 0; jb < 2; jb++) {
                uint32_t bH[4], bL[4];
                ldm_x4t(bH, baddr + jb * 32);
                ldm_x4t(bL, baddr + jb * 32 + ACC_ARR);
#pragma unroll
                for (int nh = 0; nh < 2; nh++) {
                    const int idx = jb * 2 + nh;
                    mma_bf16(acc[idx], aH, &bH[nh * 2]);
                    mma_bf16(acc[idx], aH, &bL[nh * 2]);
                    mma_bf16(acc[idx], aL, &bH[nh * 2]);
                }
            }
        }
        __syncthreads();
    }

    const int mrow = warpM * 16 + (lid >> 2);
#pragma unroll
    for (int idx = 0; idx < 4; idx++) {
        const int j = warpN * 32 + idx * 8 + (lid & 3) * 2;
        float* dst = out + ((size_t)b * NS + mrow) * D_SZ + h * 64 + j;
        atomicAdd(dst,     acc[idx][0]);
        atomicAdd(dst + 1, acc[idx][1]);
        float* dst2 = dst + 8 * D_SZ;
        atomicAdd(dst2,     acc[idx][2]);
        atomicAdd(dst2 + 1, acc[idx][3]);
    }
}

// ---------------------------------------------------------------------------
extern "C" void kernel_launch(void* const* d_in, const int* in_sizes, int n_in,
                              void* d_out, int out_size) {
    const float* H     = (const float*)d_in[0];   // [8, 4096, 768]
    const float* proto = (const float*)d_in[1];   // [64, 768]
    const float* W     = (const float*)d_in[2];   // [768, 768]
    const float* s0    = (const float*)d_in[3];   // [1, 64, 768]
    float* out = (float*)d_out;                   // [8, 64, 768]
    (void)in_sizes; (void)n_in; (void)out_size;

    cudaFuncSetAttribute(k_gemm_mma, cudaFuncAttributeMaxDynamicSharedMemorySize,
                         GEMM_SMEM);
    cudaFuncSetAttribute(k_accum_mma, cudaFuncAttributeMaxDynamicSharedMemorySize,
                         ACC_SMEM);

    k_split<<<(BT * D_SZ / 4) / 256, 256>>>((const float4*)H);
    k_build_C<<<(HM * D_SZ + 255) / 256, 256>>>(W, proto);

    dim3 g1(HM / 128, BT / 128);   // (6, 256)
    k_gemm_mma<<<g1, 256, GEMM_SMEM>>>();

    k_scan_b<<<B_SZ * NH, 64>>>();
    dim3 g3(B_SZ * NH, 8);
    k_scan_c<<<g3, 1024>>>();

    k_init_out<<<(B_SZ * NS * D_SZ + 255) / 256, 256>>>(s0, out);

    dim3 g4(B_SZ * NH, 4);
    k_accum_mma<<<g4, 256, ACC_SMEM>>>(out);
}

// round 15
// speedup vs baseline: 2.6673x; 1.0003x over previous
#include <cuda_runtime.h>
#include <cuda_bf16.h>
#include <cstdint>

// Problem constants
#define B_SZ   8
#define T_SZ   4096
#define D_SZ   768
#define NH     12
#define HD     64
#define NS     64
#define ALPHAF 0.1f
#define BT     (B_SZ * T_SZ)   // 32768
#define HM     (NH * NS)       // 768

// Scratch (static device globals: allocation APIs are forbidden)
__device__ __nv_bfloat16 g_Ah[(size_t)BT * D_SZ];   // H hi, 48MB
__device__ __nv_bfloat16 g_Al[(size_t)BT * D_SZ];   // H lo, 48MB
__device__ __nv_bfloat16 g_Ch[HM * D_SZ];           // C hi
__device__ __nv_bfloat16 g_Cl[HM * D_SZ];           // C lo
__device__ __nv_bfloat16 g_wh[(size_t)BT * HM];     // w hi (bf16), 48MB
__device__ __nv_bfloat16 g_wl[(size_t)BT * HM];     // w lo (bf16), 48MB
__device__ float g_res[B_SZ * NH * NS];             // total suffix product
__device__ float g_cp[B_SZ * NH * 128 * 64];        // 32-t chunk products/offsets

// ============================ helpers ======================================
__device__ __forceinline__ uint32_t smem_u32(const void* p) {
    uint32_t a;
    asm("{ .reg .u64 t; cvta.to.shared.u64 t, %1; cvt.u32.u64 %0, t; }"
        : "=r"(a) : "l"(p));
    return a;
}
// result = {hi16 = bf16(h), lo16 = bf16(l)}  (memory order: l then h)
__device__ __forceinline__ uint32_t cvt_bf16x2(float h, float l) {
    uint32_t r;
    asm("cvt.rn.bf16x2.f32 %0, %1, %2;" : "=r"(r) : "f"(h), "f"(l));
    return r;
}
// unpack hi/lo bf16-pair words into two fp32 (even = low halves, odd = high)
__device__ __forceinline__ void unpack_w(uint32_t h, uint32_t l, float& e, float& o) {
    e = __uint_as_float(h << 16) + __uint_as_float(l << 16);
    o = __uint_as_float(h & 0xFFFF0000u) + __uint_as_float(l & 0xFFFF0000u);
}
__device__ __forceinline__ void ldm_x4(uint32_t* r, uint32_t addr) {
    asm volatile("ldmatrix.sync.aligned.m8n8.x4.shared.b16 {%0,%1,%2,%3}, [%4];"
        : "=r"(r[0]), "=r"(r[1]), "=r"(r[2]), "=r"(r[3]) : "r"(addr));
}
__device__ __forceinline__ void ldm_x4t(uint32_t* r, uint32_t addr) {
    asm volatile("ldmatrix.sync.aligned.m8n8.x4.trans.shared.b16 {%0,%1,%2,%3}, [%4];"
        : "=r"(r[0]), "=r"(r[1]), "=r"(r[2]), "=r"(r[3]) : "r"(addr));
}
__device__ __forceinline__ void mma_bf16(float* d, const uint32_t* a, const uint32_t* b) {
    asm volatile(
        "mma.sync.aligned.m16n8k16.row.col.f32.bf16.bf16.f32 "
        "{%0,%1,%2,%3}, {%4,%5,%6,%7}, {%8,%9}, {%0,%1,%2,%3};"
        : "+f"(d[0]), "+f"(d[1]), "+f"(d[2]), "+f"(d[3])
        : "r"(a[0]), "r"(a[1]), "r"(a[2]), "r"(a[3]), "r"(b[0]), "r"(b[1]));
}
__device__ __forceinline__ void cp16(uint32_t dst, const void* src) {
    asm volatile("cp.async.cg.shared.global [%0], [%1], 16;" :: "r"(dst), "l"(src));
}
#define CP_COMMIT() asm volatile("cp.async.commit_group;" ::: "memory")
#define CP_WAIT(n)  asm volatile("cp.async.wait_group %0;" :: "n"(n) : "memory")

// ---------------------------------------------------------------------------
// K_split: H fp32 -> bf16 hi/lo arrays (one-time).
// ---------------------------------------------------------------------------
__global__ void __launch_bounds__(256) k_split(const float4* __restrict__ H4) {
    size_t i = (size_t)blockIdx.x * 256 + threadIdx.x;   // over BT*768/4
    float4 v = H4[i];
    uint32_t h01 = cvt_bf16x2(v.y, v.x);
    uint32_t h23 = cvt_bf16x2(v.w, v.z);
    float f0 = __uint_as_float(h01 << 16);
    float f1 = __uint_as_float(h01 & 0xFFFF0000u);
    float f2 = __uint_as_float(h23 << 16);
    float f3 = __uint_as_float(h23 & 0xFFFF0000u);
    ((uint2*)g_Ah)[i] = make_uint2(h01, h23);
    ((uint2*)g_Al)[i] = make_uint2(cvt_bf16x2(v.y - f1, v.x - f0),
                                   cvt_bf16x2(v.w - f3, v.z - f2));
}

// ---------------------------------------------------------------------------
// K0: C[h*64+m, d] = (1/8) * sum_j W_tok[h*64+j, d] * proto[m*768 + h*64 + j]
// ---------------------------------------------------------------------------
__global__ void k_build_C(const float* __restrict__ W, const float* __restrict__ proto) {
    int idx = blockIdx.x * blockDim.x + threadIdx.x;
    if (idx >= HM * D_SZ) return;
    int d  = idx % D_SZ;
    int hm = idx / D_SZ;
    int h = hm / NS, m = hm % NS;
    const float* wcol = W + (size_t)(h * HD) * D_SZ + d;
    const float* prow = proto + (size_t)m * D_SZ + h * HD;
    float acc = 0.f;
#pragma unroll 8
    for (int j = 0; j < HD; j++) acc += wcol[(size_t)j * D_SZ] * prow[j];
    acc *= 0.125f;
    __nv_bfloat16 hi = __float2bfloat16(acc);
    g_Ch[idx] = hi;
    g_Cl[idx] = __float2bfloat16(acc - __bfloat162float(hi));
}

// ---------------------------------------------------------------------------
// K1: mma.sync bf16x3 GEMM (scores) + fused softmax + fused 32-t band
//     products. Writes w as bf16 hi/lo pairs (g_wh/g_wl).
// CTA tile 128(bt) x 128(2 heads); 8 warps 4(m)x2(n); warp 32x64 = full head.
// ---------------------------------------------------------------------------
#define ARR_BYTES   10240                 // 128 * 80
#define STG_BYTES   40960                 // 4 arrays
#define GEMM_SMEM   (2 * STG_BYTES)       // 81920 -> 2 CTAs/SM

__global__ void __launch_bounds__(256, 2) k_gemm_mma() {
    extern __shared__ char smem[];
    const uint32_t sbase = smem_u32(smem);
    const int tid = threadIdx.x;
    const int wid = tid >> 5;
    const int lid = tid & 31;
    const int warpM = wid & 3;
    const int warpN = wid >> 2;
    const int m0 = blockIdx.y * 128;
    const int n0 = blockIdx.x * 128;

    auto issue = [&](int kt) {
        const uint32_t sb = sbase + (kt & 1) * STG_BYTES;
        const int koff = kt * 32;
#pragma unroll
        for (int i = 0; i < 8; i++) {
            const int arr = i >> 1;
            const int rem = tid + 256 * (i & 1);
            const int row = rem >> 2;
            const int q   = rem & 3;
            const __nv_bfloat16* src =
                (arr == 0 ? g_Ah + (size_t)(m0 + row) * D_SZ :
                 arr == 1 ? g_Al + (size_t)(m0 + row) * D_SZ :
                 arr == 2 ? g_Ch + (size_t)(n0 + row) * D_SZ :
                            g_Cl + (size_t)(n0 + row) * D_SZ) + koff + q * 8;
            cp16(sb + arr * ARR_BYTES + row * 80 + q * 16, src);
        }
        CP_COMMIT();
    };

    float acc[2][8][4];
#pragma unroll
    for (int mf = 0; mf < 2; mf++)
#pragma unroll
        for (int nf = 0; nf < 8; nf++)
#pragma unroll
            for (int c = 0; c < 4; c++) acc[mf][nf][c] = 0.f;

    const int a_row_add = (lid & 7) + ((lid >> 3) & 1) * 8;
    const int a_k_add   = (lid >> 4) * 16;
    const int b_row_add = (lid & 7) + ((lid >> 4) & 1) * 8;
    const int b_k_add   = ((lid >> 3) & 1) * 16;

    auto domath = [&](int s) {
        const uint32_t stg = sbase + s * STG_BYTES;
#pragma unroll
        for (int ks = 0; ks < 2; ks++) {
            const int kB = ks * 32;
            uint32_t aH[2][4], aL[2][4];
#pragma unroll
            for (int mf = 0; mf < 2; mf++) {
                int row = warpM * 32 + mf * 16 + a_row_add;
                uint32_t addr = stg + (uint32_t)(row * 80 + kB + a_k_add);
                ldm_x4(aH[mf], addr);
                ldm_x4(aL[mf], addr + ARR_BYTES);
            }
#pragma unroll
            for (int nf2 = 0; nf2 < 4; nf2++) {
                int nrow = warpN * 64 + nf2 * 16 + b_row_add;
                uint32_t addr = stg + 2 * ARR_BYTES + (uint32_t)(nrow * 80 + kB + b_k_add);
                uint32_t bH[4], bL[4];
                ldm_x4(bH, addr);
                ldm_x4(bL, addr + ARR_BYTES);
#pragma unroll
                for (int mf = 0; mf < 2; mf++)
#pragma unroll
                    for (int nh = 0; nh < 2; nh++) {
                        const int nf = nf2 * 2 + nh;
                        mma_bf16(acc[mf][nf], aH[mf], &bH[nh * 2]);
                        mma_bf16(acc[mf][nf], aH[mf], &bL[nh * 2]);
                        mma_bf16(acc[mf][nf], aL[mf], &bH[nh * 2]);
                    }
            }
        }
    };

    const int KT = D_SZ / 32;  // 24
    issue(0);
    for (int kt = 0; kt < KT; kt++) {
        if (kt + 1 < KT) { issue(kt + 1); CP_WAIT(1); }
        else             { CP_WAIT(0); }
        __syncthreads();
        domath(kt & 1);
        __syncthreads();
    }

    // Epilogue: softmax per row (warp's 64-col head); write w as bf16 hi/lo;
    // accumulate per-lane products of (1 - alpha*w) over this warp's 32 rows.
    const int colq = (lid & 3) * 2;
    const int coloff = n0 + warpN * 64 + colq;
    float pl[8][2];
#pragma unroll
    for (int nf = 0; nf < 8; nf++) { pl[nf][0] = 1.f; pl[nf][1] = 1.f; }

#pragma unroll
    for (int mf = 0; mf < 2; mf++) {
#pragma unroll
        for (int half = 0; half < 2; half++) {
            const int row = m0 + warpM * 32 + mf * 16 + (lid >> 2) + half * 8;
            float mx = -3.4e38f;
#pragma unroll
            for (int nf = 0; nf < 8; nf++) {
                mx = fmaxf(mx, acc[mf][nf][half * 2]);
                mx = fmaxf(mx, acc[mf][nf][half * 2 + 1]);
            }
            mx = fmaxf(mx, __shfl_xor_sync(0xFFFFFFFFu, mx, 1));
            mx = fmaxf(mx, __shfl_xor_sync(0xFFFFFFFFu, mx, 2));
            float s = 0.f;
            float ev[8][2];
#pragma unroll
            for (int nf = 0; nf < 8; nf++) {
                ev[nf][0] = __expf(acc[mf][nf][half * 2]     - mx);
                ev[nf][1] = __expf(acc[mf][nf][half * 2 + 1] - mx);
                s += ev[nf][0] + ev[nf][1];
            }
            s += __shfl_xor_sync(0xFFFFFFFFu, s, 1);
            s += __shfl_xor_sync(0xFFFFFFFFu, s, 2);
            const float inv = 1.0f / s;
            const size_t rbase = (size_t)row * HM + coloff;
#pragma unroll
            for (int nf = 0; nf < 8; nf++) {
                float w0 = ev[nf][0] * inv;
                float w1 = ev[nf][1] * inv;
                uint32_t hp = cvt_bf16x2(w1, w0);
                float b0 = __uint_as_float(hp << 16);
                float b1 = __uint_as_float(hp & 0xFFFF0000u);
                uint32_t lp = cvt_bf16x2(w1 - b1, w0 - b0);
                *(uint32_t*)(g_wh + rbase + nf * 8) = hp;
                *(uint32_t*)(g_wl + rbase + nf * 8) = lp;
                pl[nf][0] *= fmaf(-ALPHAF, w0, 1.f);
                pl[nf][1] *= fmaf(-ALPHAF, w1, 1.f);
            }
        }
    }

    // Combine across the 8 lane-rows sharing the same columns -> band product
    // over this warp's 32 t-rows.
#pragma unroll
    for (int off = 4; off <= 16; off <<= 1)
#pragma unroll
        for (int nf = 0; nf < 8; nf++) {
            pl[nf][0] *= __shfl_xor_sync(0xFFFFFFFFu, pl[nf][0], off);
            pl[nf][1] *= __shfl_xor_sync(0xFFFFFFFFu, pl[nf][1], off);
        }

    if (lid < 4) {
        const int b    = m0 >> 12;
        const int tch  = (m0 & 4095) >> 7;         // 128-t tile index 0..31
        const int sub  = tch * 4 + warpM;          // 32-t chunk index 0..127
        const int head = (n0 >> 6) + warpN;
        float* dst = g_cp + ((size_t)(b * NH + head) * 128 + sub) * 64;
#pragma unroll
        for (int nf = 0; nf < 8; nf++) {
            dst[colq + nf * 8]     = pl[nf][0];
            dst[colq + nf * 8 + 1] = pl[nf][1];
        }
    }
}

// ---------------------------------------------------------------------------
// K3b: suffix combine across 128 chunks (parallel, 512 thr: 64 m x 8 groups).
// g_cp -> exclusive-suffix offsets; g_res = total product.
// ---------------------------------------------------------------------------
__global__ void __launch_bounds__(512) k_scan_b() {
    __shared__ float part[8][64];
    const int bh = blockIdx.x;
    const int m  = threadIdx.x & 63;
    const int cg = threadIdx.x >> 6;       // 0..7, 16 chunks each
    const size_t base = ((size_t)bh * 128 + cg * 16) * 64 + m;
    float v[16];
    float p = 1.f;
#pragma unroll
    for (int i = 0; i < 16; i++) { v[i] = g_cp[base + (size_t)i * 64]; p *= v[i]; }
    part[cg][m] = p;
    __syncthreads();
    float run = 1.f;
#pragma unroll
    for (int c2 = 7; c2 > 0; c2--) if (c2 > cg) run *= part[c2][m];
    if (cg == 0) g_res[bh * 64 + m] = run * p;
#pragma unroll
    for (int i = 15; i >= 0; i--) {
        float val = v[i];
        g_cp[base + (size_t)i * 64] = run;   // exclusive suffix at chunk i
        run *= val;
    }
}

// ---------------------------------------------------------------------------
// K4a: out init with s0 * residual
// ---------------------------------------------------------------------------
__global__ void k_init_out(const float* __restrict__ s0, float* __restrict__ out) {
    int idx = blockIdx.x * blockDim.x + threadIdx.x;
    if (idx >= B_SZ * NS * D_SZ) return;
    int dj = idx % D_SZ;
    int m  = (idx / D_SZ) % NS;
    int b  = idx / (D_SZ * NS);
    int h  = dj / HD;
    out[idx] = s0[(size_t)m * D_SZ + dj] * g_res[(b * NH + h) * NS + m];
}

// ---------------------------------------------------------------------------
// K4b (mma): out[b, m, h*64+j] += sum_t w_eff[t,m] * H[t, h*64+j]
// Per block: (bh, tsplit of 1024). Raw w tiles (bf16 hi/lo) are loaded via
// cp.async, converted IN-PLACE in smem to w_eff (suffix-product scan using
// g_cp chunk offsets), then consumed by trans-ldmatrix + mma.
// ---------------------------------------------------------------------------
#define ACC_ARR  9216       // 64 * 144
#define ACC_STG  36864      // 4 arrays
#define ACC_SCR  2048       // partial-product scratch (2*4*32*2 floats = 512 f)
#define ACC_SMEM (2 * ACC_STG + ACC_SCR)   // 75776

__global__ void __launch_bounds__(256, 2) k_accum_mma(float* __restrict__ out) {
    extern __shared__ char smem[];
    const uint32_t sbase = smem_u32(smem);
    const int tid = threadIdx.x;
    const int lid = tid & 31;
    const int wid = tid >> 5;
    const int warpM = wid & 3;
    const int warpN = wid >> 2;
    const int bh = blockIdx.x;
    const int b = bh / NH, h = bh % NH;
    const int t0 = blockIdx.y * 1024;
    const size_t rowbase = ((size_t)b * T_SZ + t0) * (size_t)HM + h * 64;

    auto issue = [&](int c) {
        const uint32_t sb = sbase + (c & 1) * ACC_STG;
        const int tch = c * 64;
#pragma unroll
        for (int i = 0; i < 8; i++) {
            const int arr = i >> 1;
            const int rem = tid + 256 * (i & 1);
            const int row = rem >> 3;
            const int q   = rem & 7;
            const size_t so = rowbase + (size_t)(tch + row) * HM + q * 8;
            const __nv_bfloat16* src =
                (arr == 0 ? g_wh : arr == 1 ? g_wl : arr == 2 ? g_Ah : g_Al) + so;
            cp16(sb + arr * ACC_ARR + row * 144 + q * 16, src);
        }
        CP_COMMIT();
    };

    float acc[4][4];
#pragma unroll
    for (int i = 0; i < 4; i++)
#pragma unroll
        for (int j = 0; j < 4; j++) acc[i][j] = 0.f;

    const int ar = (lid & 7) + (lid >> 4) * 8;
    const int ab = ((lid >> 3) & 1) * 16;
    const int br = (lid & 7) + ((lid >> 3) & 1) * 8;
    const int bb = (lid >> 4) * 16;

    // scan thread mapping: 256 = 32 m-pairs x 2 sub-chunks x 4 t-groups
    const int s_m2  = tid & 31;
    const int s_c32 = (tid >> 5) & 1;
    const int s_tg  = tid >> 6;            // 0..3, 8 t's each
    float* scr = (float*)(smem + 2 * ACC_STG);   // [c32][tg][m2][2] = 512 floats

    issue(0);
    for (int c = 0; c < 16; c++) {
        if (c + 1 < 16) { issue(c + 1); CP_WAIT(1); }
        else            { CP_WAIT(0); }
        __syncthreads();
        const uint32_t sb = sbase + (c & 1) * ACC_STG;

        // ---- in-place w -> w_eff conversion ----
        {
            uint32_t rh[8], rl[8];
            float pe = 1.f, po = 1.f;
#pragma unroll
            for (int s = 0; s < 8; s++) {
                const uint32_t addr = sb +
                    (uint32_t)((s_c32 * 32 + s_tg * 8 + s) * 144 + s_m2 * 4);
                asm volatile("ld.shared.b32 %0, [%1];" : "=r"(rh[s]) : "r"(addr));
                asm volatile("ld.shared.b32 %0, [%1];" : "=r"(rl[s]) : "r"(addr + ACC_ARR));
                float we, wo;
                unpack_w(rh[s], rl[s], we, wo);
                pe *= fmaf(-ALPHAF, we, 1.f);
                po *= fmaf(-ALPHAF, wo, 1.f);
            }
            const int sidx = ((s_c32 * 4 + s_tg) * 32 + s_m2) * 2;
            scr[sidx]     = pe;
            scr[sidx + 1] = po;
            __syncthreads();
            const int cig = blockIdx.y * 32 + c * 2 + s_c32;   // global 32-t chunk
            const size_t cpbase = ((size_t)bh * 128 + cig) * 64 + s_m2 * 2;
            float rune = g_cp[cpbase];
            float runo = g_cp[cpbase + 1];
#pragma unroll
            for (int tgp = 1; tgp < 4; tgp++)
                if (tgp > s_tg) {
                    const int pidx = ((s_c32 * 4 + tgp) * 32 + s_m2) * 2;
                    rune *= scr[pidx];
                    runo *= scr[pidx + 1];
                }
#pragma unroll
            for (int s = 7; s >= 0; s--) {
                const uint32_t addr = sb +
                    (uint32_t)((s_c32 * 32 + s_tg * 8 + s) * 144 + s_m2 * 4);
                float we, wo;
                unpack_w(rh[s], rl[s], we, wo);
                float vee = ALPHAF * we * rune;
                float veo = ALPHAF * wo * runo;
                uint32_t hp = cvt_bf16x2(veo, vee);
                float be = __uint_as_float(hp << 16);
                float bo = __uint_as_float(hp & 0xFFFF0000u);
                uint32_t lp = cvt_bf16x2(veo - bo, vee - be);
                asm volatile("st.shared.b32 [%0], %1;" :: "r"(addr), "r"(hp));
                asm volatile("st.shared.b32 [%0], %1;" :: "r"(addr + ACC_ARR), "r"(lp));
                rune *= fmaf(-ALPHAF, we, 1.f);
                runo *= fmaf(-ALPHAF, wo, 1.f);
            }
            __syncthreads();
        }

        // ---- mma over the converted tile ----
#pragma unroll
        for (int ks = 0; ks < 4; ks++) {
            uint32_t aaddr = sb + (uint32_t)((ks * 16 + ar) * 144 + warpM * 32 + ab);
            uint32_t aH[4], aL[4];
            ldm_x4t(aH, aaddr);
            ldm_x4t(aL, aaddr + ACC_ARR);
            uint32_t baddr = sb + 2 * ACC_ARR +
                             (uint32_t)((ks * 16 + br) * 144 + warpN * 64 + bb);
#pragma unroll
            for (int jb = 0; jb < 2; jb++) {
                uint32_t bH[4], bL[4];
                ldm_x4t(bH, baddr + jb * 32);
                ldm_x4t(bL, baddr + jb * 32 + ACC_ARR);
#pragma unroll
                for (int nh = 0; nh < 2; nh++) {
                    const int idx = jb * 2 + nh;
                    mma_bf16(acc[idx], aH, &bH[nh * 2]);
                    mma_bf16(acc[idx], aH, &bL[nh * 2]);
                    mma_bf16(acc[idx], aL, &bH[nh * 2]);
                }
            }
        }
        __syncthreads();
    }

    const int mrow = warpM * 16 + (lid >> 2);
#pragma unroll
    for (int idx = 0; idx < 4; idx++) {
        const int j = warpN * 32 + idx * 8 + (lid & 3) * 2;
        float* dst = out + ((size_t)b * NS + mrow) * D_SZ + h * 64 + j;
        atomicAdd(dst,     acc[idx][0]);
        atomicAdd(dst + 1, acc[idx][1]);
        float* dst2 = dst + 8 * D_SZ;
        atomicAdd(dst2,     acc[idx][2]);
        atomicAdd(dst2 + 1, acc[idx][3]);
    }
}

// ---------------------------------------------------------------------------
extern "C" void kernel_launch(void* const* d_in, const int* in_sizes, int n_in,
                              void* d_out, int out_size) {
    const float* H     = (const float*)d_in[0];   // [8, 4096, 768]
    const float* proto = (const float*)d_in[1];   // [64, 768]
    const float* W     = (const float*)d_in[2];   // [768, 768]
    const float* s0    = (const float*)d_in[3];   // [1, 64, 768]
    float* out = (float*)d_out;                   // [8, 64, 768]
    (void)in_sizes; (void)n_in; (void)out_size;

    cudaFuncSetAttribute(k_gemm_mma, cudaFuncAttributeMaxDynamicSharedMemorySize,
                         GEMM_SMEM);
    cudaFuncSetAttribute(k_accum_mma, cudaFuncAttributeMaxDynamicSharedMemorySize,
                         ACC_SMEM);

    k_split<<<(BT * D_SZ / 4) / 256, 256>>>((const float4*)H);
    k_build_C<<<(HM * D_SZ + 255) / 256, 256>>>(W, proto);

    dim3 g1(HM / 128, BT / 128);   // (6, 256)
    k_gemm_mma<<<g1, 256, GEMM_SMEM>>>();

    k_scan_b<<<B_SZ * NH, 512>>>();

    k_init_out<<<(B_SZ * NS * D_SZ + 255) / 256, 256>>>(s0, out);

    dim3 g4(B_SZ * NH, 4);
    k_accum_mma<<<g4, 256, ACC_SMEM>>>(out);
}

// round 16
// speedup vs baseline: 5.6736x; 2.1271x over previous
#include <cuda_runtime.h>
#include <cuda_fp16.h>
#include <cstdint>

// Problem constants
#define B_SZ   8
#define T_SZ   4096
#define D_SZ   768
#define NH     12
#define HD     64
#define NS     64
#define ALPHAF 0.1f
#define BT     (B_SZ * T_SZ)   // 32768
#define HM     (NH * NS)       // 768

// fp16 scaling (keep small weights in normal range)
#define WSCALE 256.0f          // stored w = w * 256
#define WINV   (1.0f / 256.0f)
#define AW     (ALPHAF / 256.0f)          // alpha * (stored w) -> alpha*w
#define EMUL   (ALPHAF * 1024.0f / 256.0f) // stored w_eff = alpha*w*run*1024
#define OUTSC  (1.0f / 1024.0f)

// Scratch (static device globals: allocation APIs are forbidden)
__device__ __half g_Af[(size_t)BT * D_SZ];   // H fp16, 48MB
__device__ __half g_Cf[HM * D_SZ];           // C fp16
__device__ __half g_wf[(size_t)BT * HM];     // w * 256 (fp16), 48MB
__device__ float g_res[B_SZ * NH * NS];      // total suffix product
__device__ float g_cp[B_SZ * NH * 128 * 64]; // 32-t chunk products/offsets

// ============================ helpers ======================================
__device__ __forceinline__ uint32_t smem_u32(const void* p) {
    uint32_t a;
    asm("{ .reg .u64 t; cvta.to.shared.u64 t, %1; cvt.u32.u64 %0, t; }"
        : "=r"(a) : "l"(p));
    return a;
}
// result = {hi16 = f16(h), lo16 = f16(l)}
__device__ __forceinline__ uint32_t cvt_f16x2(float h, float l) {
    uint32_t r;
    asm("cvt.rn.f16x2.f32 %0, %1, %2;" : "=r"(r) : "f"(h), "f"(l));
    return r;
}
__device__ __forceinline__ void ldm_x4(uint32_t* r, uint32_t addr) {
    asm volatile("ldmatrix.sync.aligned.m8n8.x4.shared.b16 {%0,%1,%2,%3}, [%4];"
        : "=r"(r[0]), "=r"(r[1]), "=r"(r[2]), "=r"(r[3]) : "r"(addr));
}
__device__ __forceinline__ void ldm_x4t(uint32_t* r, uint32_t addr) {
    asm volatile("ldmatrix.sync.aligned.m8n8.x4.trans.shared.b16 {%0,%1,%2,%3}, [%4];"
        : "=r"(r[0]), "=r"(r[1]), "=r"(r[2]), "=r"(r[3]) : "r"(addr));
}
__device__ __forceinline__ void mma_f16(float* d, const uint32_t* a, const uint32_t* b) {
    asm volatile(
        "mma.sync.aligned.m16n8k16.row.col.f32.f16.f16.f32 "
        "{%0,%1,%2,%3}, {%4,%5,%6,%7}, {%8,%9}, {%0,%1,%2,%3};"
        : "+f"(d[0]), "+f"(d[1]), "+f"(d[2]), "+f"(d[3])
        : "r"(a[0]), "r"(a[1]), "r"(a[2]), "r"(a[3]), "r"(b[0]), "r"(b[1]));
}
__device__ __forceinline__ void cp16(uint32_t dst, const void* src) {
    asm volatile("cp.async.cg.shared.global [%0], [%1], 16;" :: "r"(dst), "l"(src));
}
#define CP_COMMIT() asm volatile("cp.async.commit_group;" ::: "memory")
#define CP_WAIT(n)  asm volatile("cp.async.wait_group %0;" :: "n"(n) : "memory")

// ---------------------------------------------------------------------------
// K_split: H fp32 -> fp16 (one-time).
// ---------------------------------------------------------------------------
__global__ void __launch_bounds__(256) k_split(const float4* __restrict__ H4) {
    size_t i = (size_t)blockIdx.x * 256 + threadIdx.x;   // over BT*768/4
    float4 v = H4[i];
    uint32_t h01 = cvt_f16x2(v.y, v.x);
    uint32_t h23 = cvt_f16x2(v.w, v.z);
    ((uint2*)g_Af)[i] = make_uint2(h01, h23);
}

// ---------------------------------------------------------------------------
// K0: C[h*64+m, d] = (1/8) * sum_j W_tok[h*64+j, d] * proto[m*768 + h*64 + j]
// ---------------------------------------------------------------------------
__global__ void k_build_C(const float* __restrict__ W, const float* __restrict__ proto) {
    int idx = blockIdx.x * blockDim.x + threadIdx.x;
    if (idx >= HM * D_SZ) return;
    int d  = idx % D_SZ;
    int hm = idx / D_SZ;
    int h = hm / NS, m = hm % NS;
    const float* wcol = W + (size_t)(h * HD) * D_SZ + d;
    const float* prow = proto + (size_t)m * D_SZ + h * HD;
    float acc = 0.f;
#pragma unroll 8
    for (int j = 0; j < HD; j++) acc += wcol[(size_t)j * D_SZ] * prow[j];
    g_Cf[idx] = __float2half(acc * 0.125f);
}

// ---------------------------------------------------------------------------
// K1: mma.sync fp16 GEMM (scores) + fused softmax + fused 32-t band products.
// CTA tile 128(bt) x 128(2 heads); 8 warps 4(m)x2(n); warp 32x64 = full head.
// 4-stage cp.async pipeline, k-chunks of 32, row pitch 80B, 2 CTAs/SM.
// ---------------------------------------------------------------------------
#define ARR_BYTES   10240                 // 128 * 80
#define STG_BYTES   20480                 // 2 arrays (A, C)
#define GEMM_SMEM   (4 * STG_BYTES)       // 81920 -> 2 CTAs/SM

__global__ void __launch_bounds__(256, 2) k_gemm_mma() {
    extern __shared__ char smem[];
    const uint32_t sbase = smem_u32(smem);
    const int tid = threadIdx.x;
    const int wid = tid >> 5;
    const int lid = tid & 31;
    const int warpM = wid & 3;
    const int warpN = wid >> 2;
    const int m0 = blockIdx.y * 128;
    const int n0 = blockIdx.x * 128;

    auto issue = [&](int kt) {
        const uint32_t sb = sbase + (kt & 3) * STG_BYTES;
        const int koff = kt * 32;
#pragma unroll
        for (int i = 0; i < 4; i++) {
            const int arr = i >> 1;                // 0: A, 1: C
            const int rem = tid + 256 * (i & 1);   // 0..511
            const int row = rem >> 2;
            const int q   = rem & 3;
            const __half* src =
                (arr == 0 ? g_Af + (size_t)(m0 + row) * D_SZ
                          : g_Cf + (size_t)(n0 + row) * D_SZ) + koff + q * 8;
            cp16(sb + arr * ARR_BYTES + row * 80 + q * 16, src);
        }
        CP_COMMIT();
    };

    float acc[2][8][4];
#pragma unroll
    for (int mf = 0; mf < 2; mf++)
#pragma unroll
        for (int nf = 0; nf < 8; nf++)
#pragma unroll
            for (int c = 0; c < 4; c++) acc[mf][nf][c] = 0.f;

    const int a_row_add = (lid & 7) + ((lid >> 3) & 1) * 8;
    const int a_k_add   = (lid >> 4) * 16;
    const int b_row_add = (lid & 7) + ((lid >> 4) & 1) * 8;
    const int b_k_add   = ((lid >> 3) & 1) * 16;

    auto domath = [&](int s) {
        const uint32_t stg = sbase + s * STG_BYTES;
#pragma unroll
        for (int ks = 0; ks < 2; ks++) {
            const int kB = ks * 32;
            uint32_t aF[2][4];
#pragma unroll
            for (int mf = 0; mf < 2; mf++) {
                int row = warpM * 32 + mf * 16 + a_row_add;
                ldm_x4(aF[mf], stg + (uint32_t)(row * 80 + kB + a_k_add));
            }
#pragma unroll
            for (int nf2 = 0; nf2 < 4; nf2++) {
                int nrow = warpN * 64 + nf2 * 16 + b_row_add;
                uint32_t bF[4];
                ldm_x4(bF, stg + ARR_BYTES + (uint32_t)(nrow * 80 + kB + b_k_add));
#pragma unroll
                for (int mf = 0; mf < 2; mf++)
#pragma unroll
                    for (int nh = 0; nh < 2; nh++)
                        mma_f16(acc[mf][nf2 * 2 + nh], aF[mf], &bF[nh * 2]);
            }
        }
    };

    const int KT = D_SZ / 32;  // 24
    issue(0); issue(1); issue(2);
    for (int kt = 0; kt < KT; kt++) {
        if (kt < KT - 2)       CP_WAIT(2);
        else if (kt == KT - 2) CP_WAIT(1);
        else                   CP_WAIT(0);
        __syncthreads();
        domath(kt & 3);
        if (kt + 3 < KT) issue(kt + 3);
    }

    // Epilogue: softmax per row (warp's 64-col head); write w*256 as fp16;
    // accumulate per-lane products of (1 - alpha*w) over this warp's 32 rows.
    const int colq = (lid & 3) * 2;
    const int coloff = n0 + warpN * 64 + colq;
    float pl[8][2];
#pragma unroll
    for (int nf = 0; nf < 8; nf++) { pl[nf][0] = 1.f; pl[nf][1] = 1.f; }

#pragma unroll
    for (int mf = 0; mf < 2; mf++) {
#pragma unroll
        for (int half = 0; half < 2; half++) {
            const int row = m0 + warpM * 32 + mf * 16 + (lid >> 2) + half * 8;
            float mx = -3.4e38f;
#pragma unroll
            for (int nf = 0; nf < 8; nf++) {
                mx = fmaxf(mx, acc[mf][nf][half * 2]);
                mx = fmaxf(mx, acc[mf][nf][half * 2 + 1]);
            }
            mx = fmaxf(mx, __shfl_xor_sync(0xFFFFFFFFu, mx, 1));
            mx = fmaxf(mx, __shfl_xor_sync(0xFFFFFFFFu, mx, 2));
            float s = 0.f;
            float ev[8][2];
#pragma unroll
            for (int nf = 0; nf < 8; nf++) {
                ev[nf][0] = __expf(acc[mf][nf][half * 2]     - mx);
                ev[nf][1] = __expf(acc[mf][nf][half * 2 + 1] - mx);
                s += ev[nf][0] + ev[nf][1];
            }
            s += __shfl_xor_sync(0xFFFFFFFFu, s, 1);
            s += __shfl_xor_sync(0xFFFFFFFFu, s, 2);
            const float inv = 1.0f / s;
            const size_t rbase = (size_t)row * HM + coloff;
#pragma unroll
            for (int nf = 0; nf < 8; nf++) {
                float w0 = ev[nf][0] * inv;
                float w1 = ev[nf][1] * inv;
                *(uint32_t*)(g_wf + rbase + nf * 8) =
                    cvt_f16x2(w1 * WSCALE, w0 * WSCALE);
                pl[nf][0] *= fmaf(-ALPHAF, w0, 1.f);
                pl[nf][1] *= fmaf(-ALPHAF, w1, 1.f);
            }
        }
    }

    // Combine across the 8 lane-rows sharing the same columns -> band product
    // over this warp's 32 t-rows.
#pragma unroll
    for (int off = 4; off <= 16; off <<= 1)
#pragma unroll
        for (int nf = 0; nf < 8; nf++) {
            pl[nf][0] *= __shfl_xor_sync(0xFFFFFFFFu, pl[nf][0], off);
            pl[nf][1] *= __shfl_xor_sync(0xFFFFFFFFu, pl[nf][1], off);
        }

    if (lid < 4) {
        const int b    = m0 >> 12;
        const int tch  = (m0 & 4095) >> 7;         // 128-t tile index 0..31
        const int sub  = tch * 4 + warpM;          // 32-t chunk index 0..127
        const int head = (n0 >> 6) + warpN;
        float* dst = g_cp + ((size_t)(b * NH + head) * 128 + sub) * 64;
#pragma unroll
        for (int nf = 0; nf < 8; nf++) {
            dst[colq + nf * 8]     = pl[nf][0];
            dst[colq + nf * 8 + 1] = pl[nf][1];
        }
    }
}

// ---------------------------------------------------------------------------
// K3b: suffix combine across 128 chunks (parallel, 512 thr: 64 m x 8 groups).
// g_cp -> exclusive-suffix offsets; g_res = total product.
// ---------------------------------------------------------------------------
__global__ void __launch_bounds__(512) k_scan_b() {
    __shared__ float part[8][64];
    const int bh = blockIdx.x;
    const int m  = threadIdx.x & 63;
    const int cg = threadIdx.x >> 6;       // 0..7, 16 chunks each
    const size_t base = ((size_t)bh * 128 + cg * 16) * 64 + m;
    float v[16];
    float p = 1.f;
#pragma unroll
    for (int i = 0; i < 16; i++) { v[i] = g_cp[base + (size_t)i * 64]; p *= v[i]; }
    part[cg][m] = p;
    __syncthreads();
    float run = 1.f;
#pragma unroll
    for (int c2 = 7; c2 > 0; c2--) if (c2 > cg) run *= part[c2][m];
    if (cg == 0) g_res[bh * 64 + m] = run * p;
#pragma unroll
    for (int i = 15; i >= 0; i--) {
        float val = v[i];
        g_cp[base + (size_t)i * 64] = run;   // exclusive suffix at chunk i
        run *= val;
    }
}

// ---------------------------------------------------------------------------
// K4a: out init with s0 * residual
// ---------------------------------------------------------------------------
__global__ void k_init_out(const float* __restrict__ s0, float* __restrict__ out) {
    int idx = blockIdx.x * blockDim.x + threadIdx.x;
    if (idx >= B_SZ * NS * D_SZ) return;
    int dj = idx % D_SZ;
    int m  = (idx / D_SZ) % NS;
    int b  = idx / (D_SZ * NS);
    int h  = dj / HD;
    out[idx] = s0[(size_t)m * D_SZ + dj] * g_res[(b * NH + h) * NS + m];
}

// ---------------------------------------------------------------------------
// K4b (mma): out[b, m, h*64+j] += sum_t w_eff[t,m] * H[t, h*64+j]
// Per block: (bh, tsplit of 1024). Raw scaled-w tiles (fp16) loaded via
// cp.async, converted IN-PLACE in smem to scaled w_eff (suffix-product scan
// using g_cp chunk offsets), then consumed by trans-ldmatrix + fp16 mma.
// Output rescaled by 1/1024 at the atomicAdd.
// ---------------------------------------------------------------------------
#define ACC_ARR  9216       // 64 * 144
#define ACC_STG  18432      // 2 arrays (w, H)
#define ACC_SCR  2048       // partial-product scratch (512 floats)
#define ACC_SMEM (2 * ACC_STG + ACC_SCR)   // 38912

__global__ void __launch_bounds__(256, 2) k_accum_mma(float* __restrict__ out) {
    extern __shared__ char smem[];
    const uint32_t sbase = smem_u32(smem);
    const int tid = threadIdx.x;
    const int lid = tid & 31;
    const int wid = tid >> 5;
    const int warpM = wid & 3;
    const int warpN = wid >> 2;
    const int bh = blockIdx.x;
    const int b = bh / NH, h = bh % NH;
    const int t0 = blockIdx.y * 1024;
    const size_t rowbase = ((size_t)b * T_SZ + t0) * (size_t)HM + h * 64;

    auto issue = [&](int c) {
        const uint32_t sb = sbase + (c & 1) * ACC_STG;
        const int tch = c * 64;
#pragma unroll
        for (int i = 0; i < 4; i++) {
            const int arr = i >> 1;               // 0: w, 1: H
            const int rem = tid + 256 * (i & 1);  // 0..511
            const int row = rem >> 3;
            const int q   = rem & 7;
            const size_t so = rowbase + (size_t)(tch + row) * HM + q * 8;
            const __half* src = (arr == 0 ? g_wf : g_Af) + so;
            cp16(sb + arr * ACC_ARR + row * 144 + q * 16, src);
        }
        CP_COMMIT();
    };

    float acc[4][4];
#pragma unroll
    for (int i = 0; i < 4; i++)
#pragma unroll
        for (int j = 0; j < 4; j++) acc[i][j] = 0.f;

    const int ar = (lid & 7) + (lid >> 4) * 8;
    const int ab = ((lid >> 3) & 1) * 16;
    const int br = (lid & 7) + ((lid >> 3) & 1) * 8;
    const int bb = (lid >> 4) * 16;

    // scan thread mapping: 256 = 32 m-pairs x 2 sub-chunks x 4 t-groups
    const int s_m2  = tid & 31;
    const int s_c32 = (tid >> 5) & 1;
    const int s_tg  = tid >> 6;            // 0..3, 8 t's each
    float* scr = (float*)(smem + 2 * ACC_STG);   // [c32][tg][m2][2] = 512 floats

    issue(0);
    for (int c = 0; c < 16; c++) {
        if (c + 1 < 16) { issue(c + 1); CP_WAIT(1); }
        else            { CP_WAIT(0); }
        __syncthreads();
        const uint32_t sb = sbase + (c & 1) * ACC_STG;

        // ---- in-place (w*256) -> (w_eff*1024) conversion ----
        {
            uint32_t rw[8];
            float pe = 1.f, po = 1.f;
#pragma unroll
            for (int s = 0; s < 8; s++) {
                const uint32_t addr = sb +
                    (uint32_t)((s_c32 * 32 + s_tg * 8 + s) * 144 + s_m2 * 4);
                asm volatile("ld.shared.b32 %0, [%1];" : "=r"(rw[s]) : "r"(addr));
                __half2 hv = *(__half2*)&rw[s];
                float2 f = __half22float2(hv);
                pe *= fmaf(-AW, f.x, 1.f);
                po *= fmaf(-AW, f.y, 1.f);
            }
            const int sidx = ((s_c32 * 4 + s_tg) * 32 + s_m2) * 2;
            scr[sidx]     = pe;
            scr[sidx + 1] = po;
            __syncthreads();
            const int cig = blockIdx.y * 32 + c * 2 + s_c32;   // global 32-t chunk
            const size_t cpbase = ((size_t)bh * 128 + cig) * 64 + s_m2 * 2;
            float rune = g_cp[cpbase];
            float runo = g_cp[cpbase + 1];
#pragma unroll
            for (int tgp = 1; tgp < 4; tgp++)
                if (tgp > s_tg) {
                    const int pidx = ((s_c32 * 4 + tgp) * 32 + s_m2) * 2;
                    rune *= scr[pidx];
                    runo *= scr[pidx + 1];
                }
#pragma unroll
            for (int s = 7; s >= 0; s--) {
                const uint32_t addr = sb +
                    (uint32_t)((s_c32 * 32 + s_tg * 8 + s) * 144 + s_m2 * 4);
                __half2 hv = *(__half2*)&rw[s];
                float2 f = __half22float2(hv);
                float vee = EMUL * f.x * rune;
                float veo = EMUL * f.y * runo;
                uint32_t packed = cvt_f16x2(veo, vee);
                asm volatile("st.shared.b32 [%0], %1;" :: "r"(addr), "r"(packed));
                rune *= fmaf(-AW, f.x, 1.f);
                runo *= fmaf(-AW, f.y, 1.f);
            }
            __syncthreads();
        }

        // ---- mma over the converted tile ----
#pragma unroll
        for (int ks = 0; ks < 4; ks++) {
            uint32_t aF[4];
            ldm_x4t(aF, sb + (uint32_t)((ks * 16 + ar) * 144 + warpM * 32 + ab));
            uint32_t baddr = sb + ACC_ARR +
                             (uint32_t)((ks * 16 + br) * 144 + warpN * 64 + bb);
#pragma unroll
            for (int jb = 0; jb < 2; jb++) {
                uint32_t bF[4];
                ldm_x4t(bF, baddr + jb * 32);
#pragma unroll
                for (int nh = 0; nh < 2; nh++)
                    mma_f16(acc[jb * 2 + nh], aF, &bF[nh * 2]);
            }
        }
        __syncthreads();
    }

    const int mrow = warpM * 16 + (lid >> 2);
#pragma unroll
    for (int idx = 0; idx < 4; idx++) {
        const int j = warpN * 32 + idx * 8 + (lid & 3) * 2;
        float* dst = out + ((size_t)b * NS + mrow) * D_SZ + h * 64 + j;
        atomicAdd(dst,     acc[idx][0] * OUTSC);
        atomicAdd(dst + 1, acc[idx][1] * OUTSC);
        float* dst2 = dst + 8 * D_SZ;
        atomicAdd(dst2,     acc[idx][2] * OUTSC);
        atomicAdd(dst2 + 1, acc[idx][3] * OUTSC);
    }
}

// ---------------------------------------------------------------------------
extern "C" void kernel_launch(void* const* d_in, const int* in_sizes, int n_in,
                              void* d_out, int out_size) {
    const float* H     = (const float*)d_in[0];   // [8, 4096, 768]
    const float* proto = (const float*)d_in[1];   // [64, 768]
    const float* W     = (const float*)d_in[2];   // [768, 768]
    const float* s0    = (const float*)d_in[3];   // [1, 64, 768]
    float* out = (float*)d_out;                   // [8, 64, 768]
    (void)in_sizes; (void)n_in; (void)out_size;

    cudaFuncSetAttribute(k_gemm_mma, cudaFuncAttributeMaxDynamicSharedMemorySize,
                         GEMM_SMEM);
    cudaFuncSetAttribute(k_accum_mma, cudaFuncAttributeMaxDynamicSharedMemorySize,
                         ACC_SMEM);

    k_split<<<(BT * D_SZ / 4) / 256, 256>>>((const float4*)H);
    k_build_C<<<(HM * D_SZ + 255) / 256, 256>>>(W, proto);

    dim3 g1(HM / 128, BT / 128);   // (6, 256)
    k_gemm_mma<<<g1, 256, GEMM_SMEM>>>();

    k_scan_b<<<B_SZ * NH, 512>>>();

    k_init_out<<<(B_SZ * NS * D_SZ + 255) / 256, 256>>>(s0, out);

    dim3 g4(B_SZ * NH, 4);
    k_accum_mma<<<g4, 256, ACC_SMEM>>>(out);
}

// round 17
// speedup vs baseline: 5.9948x; 1.0566x over previous
#include <cuda_runtime.h>
#include <cuda_fp16.h>
#include <cstdint>

// Problem constants
#define B_SZ   8
#define T_SZ   4096
#define D_SZ   768
#define NH     12
#define HD     64
#define NS     64
#define ALPHAF 0.1f
#define BT     (B_SZ * T_SZ)   // 32768
#define HM     (NH * NS)       // 768

// fp16 scaling (keep small weights in normal range)
#define WSCALE 256.0f          // stored w = w * 256
#define AW     (ALPHAF / 256.0f)           // alpha * (stored w) -> alpha*w
#define EMUL   (ALPHAF * 1024.0f / 256.0f) // stored w_eff = alpha*w*run*1024
#define OUTSC  (1.0f / 1024.0f)

// Scratch (static device globals: allocation APIs are forbidden)
__device__ __half g_Af[(size_t)BT * D_SZ];   // H fp16, 48MB
__device__ __half g_Cf[HM * D_SZ];           // C fp16
__device__ __half g_wf[(size_t)BT * HM];     // w * 256 (fp16), 48MB
__device__ float g_res[B_SZ * NH * NS];      // total suffix product
__device__ float g_cp[B_SZ * NH * 128 * 64]; // 32-t chunk products/offsets

// ============================ helpers ======================================
__device__ __forceinline__ uint32_t smem_u32(const void* p) {
    uint32_t a;
    asm("{ .reg .u64 t; cvta.to.shared.u64 t, %1; cvt.u32.u64 %0, t; }"
        : "=r"(a) : "l"(p));
    return a;
}
// result = {hi16 = f16(h), lo16 = f16(l)}
__device__ __forceinline__ uint32_t cvt_f16x2(float h, float l) {
    uint32_t r;
    asm("cvt.rn.f16x2.f32 %0, %1, %2;" : "=r"(r) : "f"(h), "f"(l));
    return r;
}
__device__ __forceinline__ void ldm_x4(uint32_t* r, uint32_t addr) {
    asm volatile("ldmatrix.sync.aligned.m8n8.x4.shared.b16 {%0,%1,%2,%3}, [%4];"
        : "=r"(r[0]), "=r"(r[1]), "=r"(r[2]), "=r"(r[3]) : "r"(addr));
}
__device__ __forceinline__ void ldm_x4t(uint32_t* r, uint32_t addr) {
    asm volatile("ldmatrix.sync.aligned.m8n8.x4.trans.shared.b16 {%0,%1,%2,%3}, [%4];"
        : "=r"(r[0]), "=r"(r[1]), "=r"(r[2]), "=r"(r[3]) : "r"(addr));
}
__device__ __forceinline__ void mma_f16(float* d, const uint32_t* a, const uint32_t* b) {
    asm volatile(
        "mma.sync.aligned.m16n8k16.row.col.f32.f16.f16.f32 "
        "{%0,%1,%2,%3}, {%4,%5,%6,%7}, {%8,%9}, {%0,%1,%2,%3};"
        : "+f"(d[0]), "+f"(d[1]), "+f"(d[2]), "+f"(d[3])
        : "r"(a[0]), "r"(a[1]), "r"(a[2]), "r"(a[3]), "r"(b[0]), "r"(b[1]));
}
__device__ __forceinline__ void cp16(uint32_t dst, const void* src) {
    asm volatile("cp.async.cg.shared.global [%0], [%1], 16;" :: "r"(dst), "l"(src));
}
#define CP_COMMIT() asm volatile("cp.async.commit_group;" ::: "memory")
#define CP_WAIT(n)  asm volatile("cp.async.wait_group %0;" :: "n"(n) : "memory")

// ---------------------------------------------------------------------------
// K_split: H fp32 -> fp16 (one-time).
// ---------------------------------------------------------------------------
__global__ void __launch_bounds__(256) k_split(const float4* __restrict__ H4) {
    size_t i = (size_t)blockIdx.x * 256 + threadIdx.x;   // over BT*768/4
    float4 v = H4[i];
    uint32_t h01 = cvt_f16x2(v.y, v.x);
    uint32_t h23 = cvt_f16x2(v.w, v.z);
    ((uint2*)g_Af)[i] = make_uint2(h01, h23);
}

// ---------------------------------------------------------------------------
// K0: C[h*64+m, d] = (1/8) * sum_j W_tok[h*64+j, d] * proto[m*768 + h*64 + j]
// ---------------------------------------------------------------------------
__global__ void k_build_C(const float* __restrict__ W, const float* __restrict__ proto) {
    int idx = blockIdx.x * blockDim.x + threadIdx.x;
    if (idx >= HM * D_SZ) return;
    int d  = idx % D_SZ;
    int hm = idx / D_SZ;
    int h = hm / NS, m = hm % NS;
    const float* wcol = W + (size_t)(h * HD) * D_SZ + d;
    const float* prow = proto + (size_t)m * D_SZ + h * HD;
    float acc = 0.f;
#pragma unroll 8
    for (int j = 0; j < HD; j++) acc += wcol[(size_t)j * D_SZ] * prow[j];
    g_Cf[idx] = __float2half(acc * 0.125f);
}

// ---------------------------------------------------------------------------
// K1: mma.sync fp16 GEMM (scores) + fused softmax + fused 32-t band products.
// CTA tile 128(bt) x 128(2 heads); 8 warps 4(m)x2(n); warp 32x64 = full head.
// 4-stage cp.async pipeline, k-chunks of 32, row pitch 80B, 2 CTAs/SM.
// ---------------------------------------------------------------------------
#define ARR_BYTES   10240                 // 128 * 80
#define STG_BYTES   20480                 // 2 arrays (A, C)
#define GEMM_SMEM   (4 * STG_BYTES)       // 81920 -> 2 CTAs/SM

__global__ void __launch_bounds__(256, 2) k_gemm_mma() {
    extern __shared__ char smem[];
    const uint32_t sbase = smem_u32(smem);
    const int tid = threadIdx.x;
    const int wid = tid >> 5;
    const int lid = tid & 31;
    const int warpM = wid & 3;
    const int warpN = wid >> 2;
    const int m0 = blockIdx.y * 128;
    const int n0 = blockIdx.x * 128;

    auto issue = [&](int kt) {
        const uint32_t sb = sbase + (kt & 3) * STG_BYTES;
        const int koff = kt * 32;
#pragma unroll
        for (int i = 0; i < 4; i++) {
            const int arr = i >> 1;                // 0: A, 1: C
            const int rem = tid + 256 * (i & 1);   // 0..511
            const int row = rem >> 2;
            const int q   = rem & 3;
            const __half* src =
                (arr == 0 ? g_Af + (size_t)(m0 + row) * D_SZ
                          : g_Cf + (size_t)(n0 + row) * D_SZ) + koff + q * 8;
            cp16(sb + arr * ARR_BYTES + row * 80 + q * 16, src);
        }
        CP_COMMIT();
    };

    float acc[2][8][4];
#pragma unroll
    for (int mf = 0; mf < 2; mf++)
#pragma unroll
        for (int nf = 0; nf < 8; nf++)
#pragma unroll
            for (int c = 0; c < 4; c++) acc[mf][nf][c] = 0.f;

    const int a_row_add = (lid & 7) + ((lid >> 3) & 1) * 8;
    const int a_k_add   = (lid >> 4) * 16;
    const int b_row_add = (lid & 7) + ((lid >> 4) & 1) * 8;
    const int b_k_add   = ((lid >> 3) & 1) * 16;

    auto domath = [&](int s) {
        const uint32_t stg = sbase + s * STG_BYTES;
#pragma unroll
        for (int ks = 0; ks < 2; ks++) {
            const int kB = ks * 32;
            uint32_t aF[2][4];
#pragma unroll
            for (int mf = 0; mf < 2; mf++) {
                int row = warpM * 32 + mf * 16 + a_row_add;
                ldm_x4(aF[mf], stg + (uint32_t)(row * 80 + kB + a_k_add));
            }
#pragma unroll
            for (int nf2 = 0; nf2 < 4; nf2++) {
                int nrow = warpN * 64 + nf2 * 16 + b_row_add;
                uint32_t bF[4];
                ldm_x4(bF, stg + ARR_BYTES + (uint32_t)(nrow * 80 + kB + b_k_add));
#pragma unroll
                for (int mf = 0; mf < 2; mf++)
#pragma unroll
                    for (int nh = 0; nh < 2; nh++)
                        mma_f16(acc[mf][nf2 * 2 + nh], aF[mf], &bF[nh * 2]);
            }
        }
    };

    const int KT = D_SZ / 32;  // 24
    issue(0); issue(1); issue(2);
    for (int kt = 0; kt < KT; kt++) {
        if (kt < KT - 2)       CP_WAIT(2);
        else if (kt == KT - 2) CP_WAIT(1);
        else                   CP_WAIT(0);
        __syncthreads();
        domath(kt & 3);
        if (kt + 3 < KT) issue(kt + 3);
    }

    // Epilogue: softmax per row (warp's 64-col head); write w*256 as fp16;
    // accumulate per-lane products of (1 - alpha*w) over this warp's 32 rows.
    const int colq = (lid & 3) * 2;
    const int coloff = n0 + warpN * 64 + colq;
    float pl[8][2];
#pragma unroll
    for (int nf = 0; nf < 8; nf++) { pl[nf][0] = 1.f; pl[nf][1] = 1.f; }

#pragma unroll
    for (int mf = 0; mf < 2; mf++) {
#pragma unroll
        for (int half = 0; half < 2; half++) {
            const int row = m0 + warpM * 32 + mf * 16 + (lid >> 2) + half * 8;
            float mx = -3.4e38f;
#pragma unroll
            for (int nf = 0; nf < 8; nf++) {
                mx = fmaxf(mx, acc[mf][nf][half * 2]);
                mx = fmaxf(mx, acc[mf][nf][half * 2 + 1]);
            }
            mx = fmaxf(mx, __shfl_xor_sync(0xFFFFFFFFu, mx, 1));
            mx = fmaxf(mx, __shfl_xor_sync(0xFFFFFFFFu, mx, 2));
            float s = 0.f;
            float ev[8][2];
#pragma unroll
            for (int nf = 0; nf < 8; nf++) {
                ev[nf][0] = __expf(acc[mf][nf][half * 2]     - mx);
                ev[nf][1] = __expf(acc[mf][nf][half * 2 + 1] - mx);
                s += ev[nf][0] + ev[nf][1];
            }
            s += __shfl_xor_sync(0xFFFFFFFFu, s, 1);
            s += __shfl_xor_sync(0xFFFFFFFFu, s, 2);
            const float inv = 1.0f / s;
            const size_t rbase = (size_t)row * HM + coloff;
#pragma unroll
            for (int nf = 0; nf < 8; nf++) {
                float w0 = ev[nf][0] * inv;
                float w1 = ev[nf][1] * inv;
                *(uint32_t*)(g_wf + rbase + nf * 8) =
                    cvt_f16x2(w1 * WSCALE, w0 * WSCALE);
                pl[nf][0] *= fmaf(-ALPHAF, w0, 1.f);
                pl[nf][1] *= fmaf(-ALPHAF, w1, 1.f);
            }
        }
    }

    // Combine across the 8 lane-rows sharing the same columns -> band product
    // over this warp's 32 t-rows.
#pragma unroll
    for (int off = 4; off <= 16; off <<= 1)
#pragma unroll
        for (int nf = 0; nf < 8; nf++) {
            pl[nf][0] *= __shfl_xor_sync(0xFFFFFFFFu, pl[nf][0], off);
            pl[nf][1] *= __shfl_xor_sync(0xFFFFFFFFu, pl[nf][1], off);
        }

    if (lid < 4) {
        const int b    = m0 >> 12;
        const int tch  = (m0 & 4095) >> 7;         // 128-t tile index 0..31
        const int sub  = tch * 4 + warpM;          // 32-t chunk index 0..127
        const int head = (n0 >> 6) + warpN;
        float* dst = g_cp + ((size_t)(b * NH + head) * 128 + sub) * 64;
#pragma unroll
        for (int nf = 0; nf < 8; nf++) {
            dst[colq + nf * 8]     = pl[nf][0];
            dst[colq + nf * 8 + 1] = pl[nf][1];
        }
    }
}

// ---------------------------------------------------------------------------
// K3b: suffix combine across 128 chunks (parallel, 512 thr: 64 m x 8 groups)
// + fused out-init (out[b, m, h-slice] = s0 * residual).
// ---------------------------------------------------------------------------
__global__ void __launch_bounds__(512) k_scan_b(const float* __restrict__ s0,
                                               float* __restrict__ out) {
    __shared__ float part[8][64];
    __shared__ float resh[64];
    const int bh = blockIdx.x;
    const int b = bh / NH, h = bh % NH;
    const int m  = threadIdx.x & 63;
    const int cg = threadIdx.x >> 6;       // 0..7, 16 chunks each
    const size_t base = ((size_t)bh * 128 + cg * 16) * 64 + m;
    float v[16];
    float p = 1.f;
#pragma unroll
    for (int i = 0; i < 16; i++) { v[i] = g_cp[base + (size_t)i * 64]; p *= v[i]; }
    part[cg][m] = p;
    __syncthreads();
    float run = 1.f;
#pragma unroll
    for (int c2 = 7; c2 > 0; c2--) if (c2 > cg) run *= part[c2][m];
    if (cg == 0) {
        float res = run * p;
        g_res[bh * 64 + m] = res;
        resh[m] = res;
    }
#pragma unroll
    for (int i = 15; i >= 0; i--) {
        float val = v[i];
        g_cp[base + (size_t)i * 64] = run;   // exclusive suffix at chunk i
        run *= val;
    }
    __syncthreads();
    // out init: 4096 elements (64 m x 64 j), 8 per thread
    const int mrow = threadIdx.x >> 3;             // 0..63
    const int j0   = (threadIdx.x & 7) * 8;        // 0,8,...,56
    const float r = resh[mrow];
    const float* sp = s0 + (size_t)mrow * D_SZ + h * HD + j0;
    float* op = out + ((size_t)b * NS + mrow) * D_SZ + h * HD + j0;
#pragma unroll
    for (int j = 0; j < 8; j += 4) {
        float4 sv = *(const float4*)(sp + j);
        float4 ov = {sv.x * r, sv.y * r, sv.z * r, sv.w * r};
        *(float4*)(op + j) = ov;
    }
}

// ---------------------------------------------------------------------------
// K4b (mma): out[b, m, h*64+j] += sum_t w_eff[t,m] * H[t, h*64+j]
// Per block: (bh, tsplit of 1024). Raw scaled-w tiles (fp16) loaded via
// cp.async, converted IN-PLACE in smem to scaled w_eff (suffix-product scan
// using g_cp chunk offsets), then consumed by trans-ldmatrix + fp16 mma.
// Output rescaled by 1/1024 at the atomicAdd. Occupancy 3 -> single wave.
// ---------------------------------------------------------------------------
#define ACC_ARR  9216       // 64 * 144
#define ACC_STG  18432      // 2 arrays (w, H)
#define ACC_SCR  2048       // partial-product scratch (512 floats)
#define ACC_SMEM (2 * ACC_STG + ACC_SCR)   // 38912

__global__ void __launch_bounds__(256, 3) k_accum_mma(float* __restrict__ out) {
    extern __shared__ char smem[];
    const uint32_t sbase = smem_u32(smem);
    const int tid = threadIdx.x;
    const int lid = tid & 31;
    const int wid = tid >> 5;
    const int warpM = wid & 3;
    const int warpN = wid >> 2;
    const int bh = blockIdx.x;
    const int b = bh / NH, h = bh % NH;
    const int t0 = blockIdx.y * 1024;
    const size_t rowbase = ((size_t)b * T_SZ + t0) * (size_t)HM + h * 64;

    auto issue = [&](int c) {
        const uint32_t sb = sbase + (c & 1) * ACC_STG;
        const int tch = c * 64;
#pragma unroll
        for (int i = 0; i < 4; i++) {
            const int arr = i >> 1;               // 0: w, 1: H
            const int rem = tid + 256 * (i & 1);  // 0..511
            const int row = rem >> 3;
            const int q   = rem & 7;
            const size_t so = rowbase + (size_t)(tch + row) * HM + q * 8;
            const __half* src = (arr == 0 ? g_wf : g_Af) + so;
            cp16(sb + arr * ACC_ARR + row * 144 + q * 16, src);
        }
        CP_COMMIT();
    };

    float acc[4][4];
#pragma unroll
    for (int i = 0; i < 4; i++)
#pragma unroll
        for (int j = 0; j < 4; j++) acc[i][j] = 0.f;

    const int ar = (lid & 7) + (lid >> 4) * 8;
    const int ab = ((lid >> 3) & 1) * 16;
    const int br = (lid & 7) + ((lid >> 3) & 1) * 8;
    const int bb = (lid >> 4) * 16;

    // scan thread mapping: 256 = 32 m-pairs x 2 sub-chunks x 4 t-groups
    const int s_m2  = tid & 31;
    const int s_c32 = (tid >> 5) & 1;
    const int s_tg  = tid >> 6;            // 0..3, 8 t's each
    float* scr = (float*)(smem + 2 * ACC_STG);   // [c32][tg][m2][2] = 512 floats

    issue(0);
    for (int c = 0; c < 16; c++) {
        if (c + 1 < 16) { issue(c + 1); CP_WAIT(1); }
        else            { CP_WAIT(0); }
        __syncthreads();
        const uint32_t sb = sbase + (c & 1) * ACC_STG;

        // ---- in-place (w*256) -> (w_eff*1024) conversion ----
        {
            uint32_t rw[8];
            float pe = 1.f, po = 1.f;
#pragma unroll
            for (int s = 0; s < 8; s++) {
                const uint32_t addr = sb +
                    (uint32_t)((s_c32 * 32 + s_tg * 8 + s) * 144 + s_m2 * 4);
                asm volatile("ld.shared.b32 %0, [%1];" : "=r"(rw[s]) : "r"(addr));
                __half2 hv = *(__half2*)&rw[s];
                float2 f = __half22float2(hv);
                pe *= fmaf(-AW, f.x, 1.f);
                po *= fmaf(-AW, f.y, 1.f);
            }
            const int sidx = ((s_c32 * 4 + s_tg) * 32 + s_m2) * 2;
            scr[sidx]     = pe;
            scr[sidx + 1] = po;
            __syncthreads();
            const int cig = blockIdx.y * 32 + c * 2 + s_c32;   // global 32-t chunk
            const size_t cpbase = ((size_t)bh * 128 + cig) * 64 + s_m2 * 2;
            float rune = g_cp[cpbase];
            float runo = g_cp[cpbase + 1];
#pragma unroll
            for (int tgp = 1; tgp < 4; tgp++)
                if (tgp > s_tg) {
                    const int pidx = ((s_c32 * 4 + tgp) * 32 + s_m2) * 2;
                    rune *= scr[pidx];
                    runo *= scr[pidx + 1];
                }
#pragma unroll
            for (int s = 7; s >= 0; s--) {
                const uint32_t addr = sb +
                    (uint32_t)((s_c32 * 32 + s_tg * 8 + s) * 144 + s_m2 * 4);
                __half2 hv = *(__half2*)&rw[s];
                float2 f = __half22float2(hv);
                float vee = EMUL * f.x * rune;
                float veo = EMUL * f.y * runo;
                uint32_t packed = cvt_f16x2(veo, vee);
                asm volatile("st.shared.b32 [%0], %1;" :: "r"(addr), "r"(packed));
                rune *= fmaf(-AW, f.x, 1.f);
                runo *= fmaf(-AW, f.y, 1.f);
            }
            __syncthreads();
        }

        // ---- mma over the converted tile ----
#pragma unroll
        for (int ks = 0; ks < 4; ks++) {
            uint32_t aF[4];
            ldm_x4t(aF, sb + (uint32_t)((ks * 16 + ar) * 144 + warpM * 32 + ab));
            uint32_t baddr = sb + ACC_ARR +
                             (uint32_t)((ks * 16 + br) * 144 + warpN * 64 + bb);
#pragma unroll
            for (int jb = 0; jb < 2; jb++) {
                uint32_t bF[4];
                ldm_x4t(bF, baddr + jb * 32);
#pragma unroll
                for (int nh = 0; nh < 2; nh++)
                    mma_f16(acc[jb * 2 + nh], aF, &bF[nh * 2]);
            }
        }
        __syncthreads();
    }

    const int mrow = warpM * 16 + (lid >> 2);
#pragma unroll
    for (int idx = 0; idx < 4; idx++) {
        const int j = warpN * 32 + idx * 8 + (lid & 3) * 2;
        float* dst = out + ((size_t)b * NS + mrow) * D_SZ + h * 64 + j;
        atomicAdd(dst,     acc[idx][0] * OUTSC);
        atomicAdd(dst + 1, acc[idx][1] * OUTSC);
        float* dst2 = dst + 8 * D_SZ;
        atomicAdd(dst2,     acc[idx][2] * OUTSC);
        atomicAdd(dst2 + 1, acc[idx][3] * OUTSC);
    }
}

// ---------------------------------------------------------------------------
extern "C" void kernel_launch(void* const* d_in, const int* in_sizes, int n_in,
                              void* d_out, int out_size) {
    const float* H     = (const float*)d_in[0];   // [8, 4096, 768]
    const float* proto = (const float*)d_in[1];   // [64, 768]
    const float* W     = (const float*)d_in[2];   // [768, 768]
    const float* s0    = (const float*)d_in[3];   // [1, 64, 768]
    float* out = (float*)d_out;                   // [8, 64, 768]
    (void)in_sizes; (void)n_in; (void)out_size;

    cudaFuncSetAttribute(k_gemm_mma, cudaFuncAttributeMaxDynamicSharedMemorySize,
                         GEMM_SMEM);
    cudaFuncSetAttribute(k_accum_mma, cudaFuncAttributeMaxDynamicSharedMemorySize,
                         ACC_SMEM);

    k_split<<<(BT * D_SZ / 4) / 256, 256>>>((const float4*)H);
    k_build_C<<<(HM * D_SZ + 255) / 256, 256>>>(W, proto);

    dim3 g1(HM / 128, BT / 128);   // (6, 256)
    k_gemm_mma<<<g1, 256, GEMM_SMEM>>>();

    k_scan_b<<<B_SZ * NH, 512>>>(s0, out);

    dim3 g4(B_SZ * NH, 4);
    k_accum_mma<<<g4, 256, ACC_SMEM>>>(out);
}